// round 1
// baseline (speedup 1.0000x reference)
#include <cuda_runtime.h>
#include <cstdint>
#include <math.h>

// ---------------- problem constants ----------------
#define BATCH 2
#define NPROP 128
#define NROI 256            // BATCH*NPROP
#define IN_CH 256
#define FH 32
#define FW 32
#define ROI 7
#define FEAT_DIM 12544      // IN_CH*ROI*ROI
#define HID 1024
#define NUM_CLASSES 21
#define NCAND 2560          // NPROP*(NUM_CLASSES-1)
#define MAX_DET 100
#define SPATIAL_SCALE (1.0f/32.0f)
#define SCORE_THRESH 0.05f
#define NMS_THRESH 0.5f
#define SPLITK 8

// ---------------- scratch (device globals; no allocations) ----------------
__device__ float g_featT[BATCH*FH*FW*IN_CH];      // NHWC transposed features
__device__ float g_X[NROI*FEAT_DIM];              // pooled roi features
__device__ float g_part[SPLITK*NROI*HID];         // split-K partials (reused)
__device__ float g_H1[NROI*HID];
__device__ float g_H2[NROI*HID];
__device__ float g_logits[NROI*NUM_CLASSES];
__device__ float g_reg[NROI*NUM_CLASSES*4];
__device__ float g_probs[NROI*NUM_CLASSES];
__device__ float g_fb[BATCH*NCAND*4];             // clipped decoded boxes
__device__ float g_fs[BATCH*NCAND];               // scores
__device__ unsigned char g_valid[BATCH*NCAND];
__device__ unsigned char g_kept[BATCH*NCAND];

// ---------------- helpers ----------------
__device__ __forceinline__ unsigned int flip_f32(float f) {
    unsigned int u = __float_as_uint(f);
    return (u & 0x80000000u) ? ~u : (u | 0x80000000u);   // monotone float->uint
}

// ---------------- 1. feature transpose NCHW -> NHWC ----------------
// features [B][256][1024(hw)] -> g_featT [B][1024][256]
__global__ void k_transpose(const float* __restrict__ f) {
    __shared__ float t[32][33];
    int b  = blockIdx.z;
    int c0 = blockIdx.y * 32;
    int w0 = blockIdx.x * 32;       // hw offset
    int tx = threadIdx.x, ty = threadIdx.y;   // (32,8)
    #pragma unroll
    for (int i = ty; i < 32; i += 8)
        t[i][tx] = f[(b*IN_CH + c0 + i)*1024 + w0 + tx];
    __syncthreads();
    #pragma unroll
    for (int i = ty; i < 32; i += 8)
        g_featT[(b*1024 + w0 + i)*IN_CH + c0 + tx] = t[tx][i];
}

// ---------------- 2. RoIAlign ----------------
// block = roi (256), threads = channels (256)
__global__ void k_roialign(const float* __restrict__ proposals) {
    int n = blockIdx.x;
    int b = n >> 7;            // /NPROP
    int c = threadIdx.x;
    const float* p = proposals + n*4;
    float x1 = p[0]*SPATIAL_SCALE, y1 = p[1]*SPATIAL_SCALE;
    float x2 = p[2]*SPATIAL_SCALE, y2 = p[3]*SPATIAL_SCALE;
    float rw = fmaxf(x2 - x1, 1.0f), rh = fmaxf(y2 - y1, 1.0f);
    float bw = rw / (float)ROI, bh = rh / (float)ROI;

    for (int ph = 0; ph < ROI; ph++) {
        for (int pw_ = 0; pw_ < ROI; pw_++) {
            float acc = 0.0f;
            #pragma unroll
            for (int sy = 0; sy < 2; sy++) {
                #pragma unroll
                for (int sx = 0; sx < 2; sx++) {
                    float gy = (float)ph + ((float)sy + 0.5f) * 0.5f;
                    float gx = (float)pw_ + ((float)sx + 0.5f) * 0.5f;
                    float y = y1 + gy * bh;
                    float x = x1 + gx * bw;
                    bool inb = (y >= -1.0f) && (y <= (float)FH) &&
                               (x >= -1.0f) && (x <= (float)FW);
                    if (!inb) continue;
                    float yc = fminf(fmaxf(y, 0.0f), (float)(FH-1));
                    float xc = fminf(fmaxf(x, 0.0f), (float)(FW-1));
                    float y0f = floorf(yc), x0f = floorf(xc);
                    int y0 = (int)y0f, x0 = (int)x0f;
                    int y1i = min(y0 + 1, FH-1), x1i = min(x0 + 1, FW-1);
                    float ly = yc - y0f, lx = xc - x0f;
                    float hy = 1.0f - ly, hx = 1.0f - lx;
                    const float* ft = g_featT;
                    float f00 = ft[(((b*FH + y0 )*FW) + x0 )*IN_CH + c];
                    float f01 = ft[(((b*FH + y0 )*FW) + x1i)*IN_CH + c];
                    float f10 = ft[(((b*FH + y1i)*FW) + x0 )*IN_CH + c];
                    float f11 = ft[(((b*FH + y1i)*FW) + x1i)*IN_CH + c];
                    acc += (hy*hx)*f00 + (hy*lx)*f01 + (ly*hx)*f10 + (ly*lx)*f11;
                }
            }
            g_X[n*FEAT_DIM + c*(ROI*ROI) + ph*ROI + pw_] = acc * 0.25f;
        }
    }
}

// ---------------- 3. GEMM (split-K partials) ----------------
// C[m,n] = sum_k A[m,k]*W[n,k] ; A [256,K] row-major, W [1024,K] row-major.
// BM=BN=128, BK=16, 256 threads, 8x8 register tile. grid (2, 8, SPLITK)
#define BM 128
#define BN 128
#define BK 16
__global__ __launch_bounds__(256, 1)
void k_gemm(const float* __restrict__ A, const float* __restrict__ W,
            float* __restrict__ Cp, int K, int kPerSplit) {
    __shared__ float As[BK][132];
    __shared__ float Bs[BK][132];

    int bm = blockIdx.x, bn = blockIdx.y, s = blockIdx.z;
    int m0 = bm * BM, n0 = bn * BN;
    int k0 = s * kPerSplit;
    int tiles = kPerSplit / BK;

    int tid = threadIdx.x;
    int ty = tid >> 4, tx = tid & 15;

    float acc[8][8];
    #pragma unroll
    for (int i = 0; i < 8; i++)
        #pragma unroll
        for (int j = 0; j < 8; j++) acc[i][j] = 0.0f;

    float4 pa[2], pb[2];
    // prefetch tile 0
    #pragma unroll
    for (int r = 0; r < 2; r++) {
        int v = tid + r*256;
        int row = v >> 2, kq = v & 3;
        pa[r] = *(const float4*)&A[(m0+row)*K + k0 + kq*4];
        pb[r] = *(const float4*)&W[(n0+row)*K + k0 + kq*4];
    }

    for (int t = 0; t < tiles; t++) {
        // store prefetched tile (transposed) to smem
        #pragma unroll
        for (int r = 0; r < 2; r++) {
            int v = tid + r*256;
            int row = v >> 2, kq = v & 3;
            As[kq*4+0][row] = pa[r].x; As[kq*4+1][row] = pa[r].y;
            As[kq*4+2][row] = pa[r].z; As[kq*4+3][row] = pa[r].w;
            Bs[kq*4+0][row] = pb[r].x; Bs[kq*4+1][row] = pb[r].y;
            Bs[kq*4+2][row] = pb[r].z; Bs[kq*4+3][row] = pb[r].w;
        }
        __syncthreads();
        // prefetch next tile (latency overlaps compute)
        if (t + 1 < tiles) {
            int kb = k0 + (t+1)*BK;
            #pragma unroll
            for (int r = 0; r < 2; r++) {
                int v = tid + r*256;
                int row = v >> 2, kq = v & 3;
                pa[r] = *(const float4*)&A[(m0+row)*K + kb + kq*4];
                pb[r] = *(const float4*)&W[(n0+row)*K + kb + kq*4];
            }
        }
        #pragma unroll
        for (int kk = 0; kk < BK; kk++) {
            float4 a0 = *(const float4*)&As[kk][ty*8];
            float4 a1 = *(const float4*)&As[kk][ty*8+4];
            float4 b0 = *(const float4*)&Bs[kk][tx*8];
            float4 b1 = *(const float4*)&Bs[kk][tx*8+4];
            float av[8] = {a0.x,a0.y,a0.z,a0.w,a1.x,a1.y,a1.z,a1.w};
            float bv[8] = {b0.x,b0.y,b0.z,b0.w,b1.x,b1.y,b1.z,b1.w};
            #pragma unroll
            for (int i = 0; i < 8; i++)
                #pragma unroll
                for (int j = 0; j < 8; j++)
                    acc[i][j] = fmaf(av[i], bv[j], acc[i][j]);
        }
        __syncthreads();
    }

    float* C = Cp + s*(NROI*HID);
    #pragma unroll
    for (int i = 0; i < 8; i++) {
        int m = m0 + ty*8 + i;
        #pragma unroll
        for (int j = 0; j < 8; j++)
            C[m*HID + n0 + tx*8 + j] = acc[i][j];
    }
}

// ---------------- 4. split-K reduce + bias + relu ----------------
__global__ void k_reduce_bias_relu(const float* __restrict__ Cp,
                                   const float* __restrict__ bias,
                                   float* __restrict__ out) {
    int i = blockIdx.x * blockDim.x + threadIdx.x;   // 0..NROI*HID
    float s = 0.0f;
    #pragma unroll
    for (int k = 0; k < SPLITK; k++) s += Cp[k*(NROI*HID) + i];
    s += bias[i & (HID-1)];
    out[i] = fmaxf(s, 0.0f);
}

// ---------------- 5. heads: cls (21) + box (84) ----------------
__global__ void k_heads(const float* __restrict__ Wc, const float* __restrict__ bc,
                        const float* __restrict__ Wb, const float* __restrict__ bb) {
    int roi = blockIdx.x;
    __shared__ float xs[HID];
    for (int k = threadIdx.x; k < HID; k += blockDim.x)
        xs[k] = g_H2[roi*HID + k];
    __syncthreads();
    int warp = threadIdx.x >> 5, lane = threadIdx.x & 31;
    for (int o = warp; o < NUM_CLASSES + NUM_CLASSES*4; o += 4) {
        const float* Wrow; float bias;
        if (o < NUM_CLASSES) { Wrow = Wc + o*HID; bias = bc[o]; }
        else { Wrow = Wb + (o - NUM_CLASSES)*HID; bias = bb[o - NUM_CLASSES]; }
        float s = 0.0f;
        for (int k = lane; k < HID; k += 32) s = fmaf(Wrow[k], xs[k], s);
        #pragma unroll
        for (int off = 16; off; off >>= 1) s += __shfl_down_sync(0xffffffffu, s, off);
        if (lane == 0) {
            s += bias;
            if (o < NUM_CLASSES) g_logits[roi*NUM_CLASSES + o] = s;
            else g_reg[roi*NUM_CLASSES*4 + (o - NUM_CLASSES)] = s;
        }
    }
}

// ---------------- 6. softmax over 21 ----------------
__global__ void k_softmax() {
    int roi = blockIdx.x * blockDim.x + threadIdx.x;
    if (roi >= NROI) return;
    const float* l = g_logits + roi*NUM_CLASSES;
    float m = -INFINITY;
    for (int c = 0; c < NUM_CLASSES; c++) m = fmaxf(m, l[c]);
    float e[NUM_CLASSES]; float sum = 0.0f;
    for (int c = 0; c < NUM_CLASSES; c++) { e[c] = expf(l[c] - m); sum += e[c]; }
    float inv = 1.0f / sum;
    for (int c = 0; c < NUM_CLASSES; c++) g_probs[roi*NUM_CLASSES + c] = e[c] * inv;
}

// ---------------- 7. decode + clip + validity ----------------
__global__ void k_decode(const float* __restrict__ proposals,
                         const int* __restrict__ img_sizes) {
    int idx = blockIdx.x * blockDim.x + threadIdx.x;    // 0..BATCH*NCAND
    if (idx >= BATCH*NCAND) return;
    int b = idx / NCAND;
    int rem = idx - b*NCAND;
    int r = rem / (NUM_CLASSES-1);
    int c = rem - r*(NUM_CLASSES-1);     // 0..19
    int cls = c + 1;
    int roi = b*NPROP + r;

    const float* p = proposals + roi*4;
    float pw = p[2] - p[0], ph = p[3] - p[1];
    float px = p[0] + pw*0.5f, py = p[1] + ph*0.5f;
    const float* d = g_reg + roi*NUM_CLASSES*4 + cls*4;
    float cx = px + d[0]*pw;
    float cy = py + d[1]*ph;
    float w  = pw * expf(d[2]);
    float h  = ph * expf(d[3]);
    float Hc = (float)img_sizes[b*2 + 0];
    float Wc = (float)img_sizes[b*2 + 1];
    float bx1 = fminf(fmaxf(cx - w*0.5f, 0.0f), Wc);
    float by1 = fminf(fmaxf(cy - h*0.5f, 0.0f), Hc);
    float bx2 = fminf(fmaxf(cx + w*0.5f, 0.0f), Wc);
    float by2 = fminf(fmaxf(cy + h*0.5f, 0.0f), Hc);

    float score = g_probs[roi*NUM_CLASSES + cls];
    int flat = r*(NUM_CLASSES-1) + c;     // matches reference flatten order
    int g = b*NCAND + flat;
    g_fb[g*4+0] = bx1; g_fb[g*4+1] = by1; g_fb[g*4+2] = bx2; g_fb[g*4+3] = by2;
    g_fs[g] = score;
    g_valid[g] = (score > SCORE_THRESH) ? 1 : 0;
    g_kept[g] = 0;
}

// ---------------- 8. per-class NMS (exactly equivalent to offset batched NMS) ----------------
// grid = BATCH*(NUM_CLASSES-1) blocks, 128 threads
__global__ void k_nms() {
    int b = blockIdx.x / (NUM_CLASSES-1);
    int c = blockIdx.x % (NUM_CLASSES-1);
    int tid = threadIdx.x;

    __shared__ unsigned long long key[NPROP];
    __shared__ float bx1[NPROP], by1[NPROP], bx2[NPROP], by2[NPROP], ar[NPROP];
    __shared__ unsigned char keep[NPROP];

    int flat = tid*(NUM_CLASSES-1) + c;
    int g = b*NCAND + flat;
    float s = g_fs[g];
    bool v = g_valid[g] != 0;
    key[tid] = v ? ((((unsigned long long)flip_f32(s)) << 32) |
                   (unsigned long long)(0xFFFFFFFFu - (unsigned)flat)) : 0ull;

    // bitonic sort descending (key carries payload)
    for (int k = 2; k <= NPROP; k <<= 1) {
        for (int j = k >> 1; j > 0; j >>= 1) {
            __syncthreads();
            int ixj = tid ^ j;
            if (ixj > tid) {
                unsigned long long a = key[tid], bb_ = key[ixj];
                bool sw = ((tid & k) == 0) ? (a < bb_) : (a > bb_);
                if (sw) { key[tid] = bb_; key[ixj] = a; }
            }
        }
    }
    __syncthreads();

    unsigned long long kk = key[tid];
    bool vj = kk != 0ull;
    int sflat = -1;
    if (vj) {
        sflat = (int)(0xFFFFFFFFu - (unsigned)(kk & 0xFFFFFFFFu));
        const float* bp = g_fb + (b*NCAND + sflat)*4;
        bx1[tid] = bp[0]; by1[tid] = bp[1]; bx2[tid] = bp[2]; by2[tid] = bp[3];
        ar[tid] = (bp[2]-bp[0]) * (bp[3]-bp[1]);
    }
    keep[tid] = vj ? 1 : 0;
    int nv = __syncthreads_count(vj ? 1 : 0);

    for (int i = 0; i < nv; i++) {
        __syncthreads();
        if (!keep[i]) continue;
        if (tid > i && keep[tid]) {
            float xi1 = fmaxf(bx1[i], bx1[tid]);
            float yi1 = fmaxf(by1[i], by1[tid]);
            float xi2 = fminf(bx2[i], bx2[tid]);
            float yi2 = fminf(by2[i], by2[tid]);
            float inter = fmaxf(xi2 - xi1, 0.0f) * fmaxf(yi2 - yi1, 0.0f);
            float iou = inter / (ar[i] + ar[tid] - inter + 1e-9f);
            if (iou > NMS_THRESH) keep[tid] = 0;
        }
    }
    __syncthreads();
    if (vj && keep[tid]) g_kept[b*NCAND + sflat] = 1;
}

// ---------------- 9. final top-100 selection + output ----------------
// grid = BATCH blocks, 1024 threads, 4096-wide bitonic sort
__global__ __launch_bounds__(1024)
void k_final(float* __restrict__ out) {
    int b = blockIdx.x;
    int tid = threadIdx.x;
    __shared__ unsigned long long key[4096];

    for (int i = tid; i < 4096; i += 1024) {
        unsigned long long k = 0ull;
        if (i < NCAND && g_kept[b*NCAND + i]) {
            float s = g_fs[b*NCAND + i];
            k = (((unsigned long long)flip_f32(s)) << 32) |
                (unsigned long long)(0xFFFFFFFFu - (unsigned)i);
        }
        key[i] = k;
    }
    for (int k = 2; k <= 4096; k <<= 1) {
        for (int j = k >> 1; j > 0; j >>= 1) {
            __syncthreads();
            for (int i = tid; i < 4096; i += 1024) {
                int ixj = i ^ j;
                if (ixj > i) {
                    unsigned long long a = key[i], bb_ = key[ixj];
                    bool sw = ((i & k) == 0) ? (a < bb_) : (a > bb_);
                    if (sw) { key[i] = bb_; key[ixj] = a; }
                }
            }
        }
    }
    __syncthreads();

    if (tid < MAX_DET) {
        unsigned long long k = key[tid];
        float b0=0,b1=0,b2=0,b3=0, sc=0, lb=0;
        if (k != 0ull) {
            int flat = (int)(0xFFFFFFFFu - (unsigned)(k & 0xFFFFFFFFu));
            const float* bp = g_fb + (b*NCAND + flat)*4;
            b0 = bp[0]; b1 = bp[1]; b2 = bp[2]; b3 = bp[3];
            sc = g_fs[b*NCAND + flat];
            lb = (float)(flat % (NUM_CLASSES-1) + 1);
        }
        // layout: boxes [B][100][4], scores [B][100], labels [B][100]
        out[b*MAX_DET*4 + tid*4 + 0] = b0;
        out[b*MAX_DET*4 + tid*4 + 1] = b1;
        out[b*MAX_DET*4 + tid*4 + 2] = b2;
        out[b*MAX_DET*4 + tid*4 + 3] = b3;
        out[BATCH*MAX_DET*4 + b*MAX_DET + tid] = sc;
        out[BATCH*MAX_DET*4 + BATCH*MAX_DET + b*MAX_DET + tid] = lb;
    }
}

__global__ void k_zero(float* o, int n) {
    int i = blockIdx.x * blockDim.x + threadIdx.x;
    if (i < n) o[i] = 0.0f;
}

// ---------------- launch ----------------
extern "C" void kernel_launch(void* const* d_in, const int* in_sizes, int n_in,
                              void* d_out, int out_size) {
    const float* features  = (const float*)d_in[0];
    const float* proposals = (const float*)d_in[1];
    const int*   img_sizes = (const int*)  d_in[2];
    const float* W1 = (const float*)d_in[3];
    const float* b1 = (const float*)d_in[4];
    const float* W2 = (const float*)d_in[5];
    const float* b2 = (const float*)d_in[6];
    const float* Wc = (const float*)d_in[7];
    const float* bc = (const float*)d_in[8];
    const float* Wb = (const float*)d_in[9];
    const float* bb = (const float*)d_in[10];
    float* out = (float*)d_out;

    float *pX, *pPart, *pH1, *pH2;
    cudaGetSymbolAddress((void**)&pX,    g_X);
    cudaGetSymbolAddress((void**)&pPart, g_part);
    cudaGetSymbolAddress((void**)&pH1,   g_H1);
    cudaGetSymbolAddress((void**)&pH2,   g_H2);

    k_zero<<<(out_size + 255)/256, 256>>>(out, out_size);

    // 1. transpose features
    k_transpose<<<dim3(32, 8, BATCH), dim3(32, 8)>>>(features);
    // 2. roi align
    k_roialign<<<NROI, IN_CH>>>(proposals);
    // 3. FC1
    k_gemm<<<dim3(NROI/BM, HID/BN, SPLITK), 256>>>(pX, W1, pPart, FEAT_DIM, FEAT_DIM/SPLITK);
    k_reduce_bias_relu<<<(NROI*HID)/256, 256>>>(pPart, b1, pH1);
    // 4. FC2
    k_gemm<<<dim3(NROI/BM, HID/BN, SPLITK), 256>>>(pH1, W2, pPart, HID, HID/SPLITK);
    k_reduce_bias_relu<<<(NROI*HID)/256, 256>>>(pPart, b2, pH2);
    // 5. heads
    k_heads<<<NROI, 128>>>(Wc, bc, Wb, bb);
    // 6. softmax
    k_softmax<<<1, NROI>>>();
    // 7. decode + clip
    k_decode<<<(BATCH*NCAND + 255)/256, 256>>>(proposals, img_sizes);
    // 8. per-class NMS
    k_nms<<<BATCH*(NUM_CLASSES-1), NPROP>>>();
    // 9. final select + write
    k_final<<<BATCH, 1024>>>(out);
}

// round 3
// speedup vs baseline: 1.2534x; 1.2534x over previous
#include <cuda_runtime.h>
#include <cstdint>
#include <math.h>

// ---------------- problem constants ----------------
#define BATCH 2
#define NPROP 128
#define NROI 256
#define IN_CH 256
#define FH 32
#define FW 32
#define ROI 7
#define FEAT_DIM 12544
#define HID 1024
#define NUM_CLASSES 21
#define NCAND 2560
#define MAX_DET 100
#define SPATIAL_SCALE (1.0f/32.0f)
#define SCORE_THRESH 0.05f
#define NMS_THRESH 0.5f
#define SPLITK 16

// ---------------- scratch ----------------
__device__ float g_featT[BATCH*FH*FW*IN_CH];
__device__ float g_X[NROI*FEAT_DIM];
__device__ float g_part[SPLITK*NROI*HID];
__device__ float g_H1[NROI*HID];
__device__ float g_H2[NROI*HID];
__device__ float g_logits[NROI*NUM_CLASSES];
__device__ float g_reg[NROI*NUM_CLASSES*4];
__device__ float g_probs[NROI*NUM_CLASSES];
__device__ float g_fb[BATCH*NCAND*4];
__device__ float g_fs[BATCH*NCAND];
__device__ unsigned char g_valid[BATCH*NCAND];
__device__ unsigned char g_kept[BATCH*NCAND];

// ---------------- helpers ----------------
__device__ __forceinline__ uint32_t smem_u32(const void* p) {
    uint32_t a;
    asm("{ .reg .u64 t; cvta.to.shared.u64 t, %1; cvt.u32.u64 %0, t; }" : "=r"(a) : "l"(p));
    return a;
}
__device__ __forceinline__ unsigned int flip_f32(float f) {
    unsigned int u = __float_as_uint(f);
    return (u & 0x80000000u) ? ~u : (u | 0x80000000u);
}
// tf32 hi part (truncate to 19 bits) + fp32 residual
__device__ __forceinline__ void splitf(float v, uint32_t& hi, uint32_t& lo) {
    uint32_t h = __float_as_uint(v) & 0xFFFFE000u;
    hi = h;
    lo = __float_as_uint(v - __uint_as_float(h));
}

__device__ __forceinline__ void mma8(float* d, const uint32_t* a, const uint32_t* b) {
    asm volatile(
        "mma.sync.aligned.m16n8k8.row.col.f32.tf32.tf32.f32 "
        "{%0,%1,%2,%3}, {%4,%5,%6,%7}, {%8,%9}, {%0,%1,%2,%3};"
        : "+f"(d[0]), "+f"(d[1]), "+f"(d[2]), "+f"(d[3])
        : "r"(a[0]), "r"(a[1]), "r"(a[2]), "r"(a[3]), "r"(b[0]), "r"(b[1]));
}

__device__ __forceinline__ void cp16(uint32_t sdst, const float* gsrc) {
    asm volatile("cp.async.cg.shared.global [%0], [%1], 16;" :: "r"(sdst), "l"(gsrc));
}

// ---------------- 1. feature transpose NCHW -> NHWC ----------------
__global__ void k_transpose(const float* __restrict__ f) {
    __shared__ float t[32][33];
    int b  = blockIdx.z;
    int c0 = blockIdx.y * 32;
    int w0 = blockIdx.x * 32;
    int tx = threadIdx.x, ty = threadIdx.y;
    #pragma unroll
    for (int i = ty; i < 32; i += 8)
        t[i][tx] = f[(b*IN_CH + c0 + i)*1024 + w0 + tx];
    __syncthreads();
    #pragma unroll
    for (int i = ty; i < 32; i += 8)
        g_featT[(b*1024 + w0 + i)*IN_CH + c0 + tx] = t[tx][i];
}

// ---------------- 2. RoIAlign ----------------
__global__ void k_roialign(const float* __restrict__ proposals) {
    int n = blockIdx.x;
    int b = n >> 7;
    int c = threadIdx.x;
    const float* p = proposals + n*4;
    float x1 = p[0]*SPATIAL_SCALE, y1 = p[1]*SPATIAL_SCALE;
    float x2 = p[2]*SPATIAL_SCALE, y2 = p[3]*SPATIAL_SCALE;
    float rw = fmaxf(x2 - x1, 1.0f), rh = fmaxf(y2 - y1, 1.0f);
    float bw = rw / (float)ROI, bh = rh / (float)ROI;

    for (int ph = 0; ph < ROI; ph++) {
        for (int pw_ = 0; pw_ < ROI; pw_++) {
            float acc = 0.0f;
            #pragma unroll
            for (int sy = 0; sy < 2; sy++) {
                #pragma unroll
                for (int sx = 0; sx < 2; sx++) {
                    float gy = (float)ph + ((float)sy + 0.5f) * 0.5f;
                    float gx = (float)pw_ + ((float)sx + 0.5f) * 0.5f;
                    float y = y1 + gy * bh;
                    float x = x1 + gx * bw;
                    bool inb = (y >= -1.0f) && (y <= (float)FH) &&
                               (x >= -1.0f) && (x <= (float)FW);
                    if (!inb) continue;
                    float yc = fminf(fmaxf(y, 0.0f), (float)(FH-1));
                    float xc = fminf(fmaxf(x, 0.0f), (float)(FW-1));
                    float y0f = floorf(yc), x0f = floorf(xc);
                    int y0 = (int)y0f, x0 = (int)x0f;
                    int y1i = min(y0 + 1, FH-1), x1i = min(x0 + 1, FW-1);
                    float ly = yc - y0f, lx = xc - x0f;
                    float hy = 1.0f - ly, hx = 1.0f - lx;
                    const float* ft = g_featT;
                    float f00 = ft[(((b*FH + y0 )*FW) + x0 )*IN_CH + c];
                    float f01 = ft[(((b*FH + y0 )*FW) + x1i)*IN_CH + c];
                    float f10 = ft[(((b*FH + y1i)*FW) + x0 )*IN_CH + c];
                    float f11 = ft[(((b*FH + y1i)*FW) + x1i)*IN_CH + c];
                    acc += (hy*hx)*f00 + (hy*lx)*f01 + (ly*hx)*f10 + (ly*lx)*f11;
                }
            }
            g_X[n*FEAT_DIM + c*(ROI*ROI) + ph*ROI + pw_] = acc * 0.25f;
        }
    }
}

// ---------------- 3. tf32x3 mma.sync GEMM ----------------
// C[m,n] = sum_k A[m,k]*W[n,k]. CTA tile 128m x 256n, BK=32, splitK over z.
// Raw fp32 tiles in SMEM (cp.async, 2 stages); hi/lo split done in registers.
#define ASTR 36
#define WSTR 36
#define A_FLOATS (128*ASTR)          // 4608
#define W_FLOATS (256*WSTR)          // 9216
#define STAGE_FLOATS (A_FLOATS + W_FLOATS)   // 13824
#define SMEM_GEMM (2*STAGE_FLOATS*4)          // 110592 bytes

__global__ __launch_bounds__(256, 1)
void k_gemm_mma(const float* __restrict__ A, const float* __restrict__ W,
                float* __restrict__ Cp, int K) {
    extern __shared__ float sm[];
    const uint32_t smb = smem_u32(sm);
    int tid = threadIdx.x;
    int wid = tid >> 5, lane = tid & 31;
    int wm = wid >> 2, wn = wid & 3;             // warp tile 64x64
    int m0 = blockIdx.x * 128;
    int n0 = blockIdx.y * 256;
    int z = blockIdx.z, Z = gridDim.z;
    int KT = K >> 5;
    int ntiles = (KT - z + Z - 1) / Z;           // k tiles: kt = z + i*Z

    float acc[4][8][4];
    #pragma unroll
    for (int i = 0; i < 4; i++)
        #pragma unroll
        for (int j = 0; j < 8; j++)
            #pragma unroll
            for (int q = 0; q < 4; q++) acc[i][j][q] = 0.0f;

    // cp.async issue for tile ti into buffer buf
    auto issue = [&](int ti, int buf) {
        int kt = z + ti * Z;
        uint32_t sa = smb + (uint32_t)(buf * STAGE_FLOATS) * 4u;
        uint32_t sw = sa + A_FLOATS * 4u;
        #pragma unroll
        for (int r = 0; r < 4; r++) {
            int t = tid + r*256;
            int row = t >> 3, q = t & 7;
            cp16(sa + (uint32_t)(row*ASTR + q*4)*4u,
                 &A[(size_t)(m0+row)*K + kt*32 + q*4]);
        }
        #pragma unroll
        for (int r = 0; r < 8; r++) {
            int t = tid + r*256;
            int row = t >> 3, q = t & 7;
            cp16(sw + (uint32_t)(row*WSTR + q*4)*4u,
                 &W[(size_t)(n0+row)*K + kt*32 + q*4]);
        }
        asm volatile("cp.async.commit_group;" ::: "memory");
    };

    issue(0, 0);

    for (int i = 0; i < ntiles; i++) {
        if (i + 1 < ntiles) {
            issue(i + 1, (i + 1) & 1);
            asm volatile("cp.async.wait_group 1;" ::: "memory");
        } else {
            asm volatile("cp.async.wait_group 0;" ::: "memory");
        }
        __syncthreads();

        const float* As = sm + (i & 1) * STAGE_FLOATS;
        const float* Ws = As + A_FLOATS;

        #pragma unroll
        for (int ks = 0; ks < 4; ks++) {
            int kc = ks*8 + (lane & 3);
            uint32_t aH[4][4], aL[4][4], wH[8][2], wL[8][2];
            #pragma unroll
            for (int mt = 0; mt < 4; mt++) {
                int r = wm*64 + mt*16 + (lane >> 2);
                splitf(As[r*ASTR + kc],        aH[mt][0], aL[mt][0]);
                splitf(As[(r+8)*ASTR + kc],    aH[mt][1], aL[mt][1]);
                splitf(As[r*ASTR + kc + 4],    aH[mt][2], aL[mt][2]);
                splitf(As[(r+8)*ASTR + kc + 4],aH[mt][3], aL[mt][3]);
            }
            #pragma unroll
            for (int nt = 0; nt < 8; nt++) {
                int n = wn*64 + nt*8 + (lane >> 2);
                splitf(Ws[n*WSTR + kc],     wH[nt][0], wL[nt][0]);
                splitf(Ws[n*WSTR + kc + 4], wH[nt][1], wL[nt][1]);
            }
            #pragma unroll
            for (int mt = 0; mt < 4; mt++)
                #pragma unroll
                for (int nt = 0; nt < 8; nt++) {
                    mma8(acc[mt][nt], aH[mt], wH[nt]);
                    mma8(acc[mt][nt], aL[mt], wH[nt]);
                    mma8(acc[mt][nt], aH[mt], wL[nt]);
                }
        }
        __syncthreads();
    }

    // epilogue: write split-K partial
    float* C = Cp + (size_t)z * (NROI*HID);
    #pragma unroll
    for (int mt = 0; mt < 4; mt++) {
        int r = m0 + wm*64 + mt*16 + (lane >> 2);
        #pragma unroll
        for (int nt = 0; nt < 8; nt++) {
            int c = n0 + wn*64 + nt*8 + (lane & 3)*2;
            *(float2*)&C[(size_t)r*HID + c]     = make_float2(acc[mt][nt][0], acc[mt][nt][1]);
            *(float2*)&C[(size_t)(r+8)*HID + c] = make_float2(acc[mt][nt][2], acc[mt][nt][3]);
        }
    }
}

// ---------------- 4. split-K reduce + bias + relu ----------------
__global__ void k_reduce_bias_relu(const float* __restrict__ Cp,
                                   const float* __restrict__ bias,
                                   float* __restrict__ out) {
    int i = blockIdx.x * blockDim.x + threadIdx.x;
    float s = 0.0f;
    #pragma unroll
    for (int k = 0; k < SPLITK; k++) s += Cp[k*(NROI*HID) + i];
    s += bias[i & (HID-1)];
    out[i] = fmaxf(s, 0.0f);
}

// ---------------- 5. heads ----------------
__global__ void k_heads(const float* __restrict__ Wc, const float* __restrict__ bc,
                        const float* __restrict__ Wb, const float* __restrict__ bb) {
    int roi = blockIdx.x;
    __shared__ float xs[HID];
    for (int k = threadIdx.x; k < HID; k += blockDim.x)
        xs[k] = g_H2[roi*HID + k];
    __syncthreads();
    int warp = threadIdx.x >> 5, lane = threadIdx.x & 31;
    for (int o = warp; o < NUM_CLASSES + NUM_CLASSES*4; o += 4) {
        const float* Wrow; float bias;
        if (o < NUM_CLASSES) { Wrow = Wc + o*HID; bias = bc[o]; }
        else { Wrow = Wb + (o - NUM_CLASSES)*HID; bias = bb[o - NUM_CLASSES]; }
        float s = 0.0f;
        for (int k = lane; k < HID; k += 32) s = fmaf(Wrow[k], xs[k], s);
        #pragma unroll
        for (int off = 16; off; off >>= 1) s += __shfl_down_sync(0xffffffffu, s, off);
        if (lane == 0) {
            s += bias;
            if (o < NUM_CLASSES) g_logits[roi*NUM_CLASSES + o] = s;
            else g_reg[roi*NUM_CLASSES*4 + (o - NUM_CLASSES)] = s;
        }
    }
}

// ---------------- 6. softmax ----------------
__global__ void k_softmax() {
    int roi = blockIdx.x * blockDim.x + threadIdx.x;
    if (roi >= NROI) return;
    const float* l = g_logits + roi*NUM_CLASSES;
    float m = -INFINITY;
    for (int c = 0; c < NUM_CLASSES; c++) m = fmaxf(m, l[c]);
    float e[NUM_CLASSES]; float sum = 0.0f;
    for (int c = 0; c < NUM_CLASSES; c++) { e[c] = expf(l[c] - m); sum += e[c]; }
    float inv = 1.0f / sum;
    for (int c = 0; c < NUM_CLASSES; c++) g_probs[roi*NUM_CLASSES + c] = e[c] * inv;
}

// ---------------- 7. decode + clip + validity ----------------
__global__ void k_decode(const float* __restrict__ proposals,
                         const int* __restrict__ img_sizes) {
    int idx = blockIdx.x * blockDim.x + threadIdx.x;
    if (idx >= BATCH*NCAND) return;
    int b = idx / NCAND;
    int rem = idx - b*NCAND;
    int r = rem / (NUM_CLASSES-1);
    int c = rem - r*(NUM_CLASSES-1);
    int cls = c + 1;
    int roi = b*NPROP + r;

    const float* p = proposals + roi*4;
    float pw = p[2] - p[0], ph = p[3] - p[1];
    float px = p[0] + pw*0.5f, py = p[1] + ph*0.5f;
    const float* d = g_reg + roi*NUM_CLASSES*4 + cls*4;
    float cx = px + d[0]*pw;
    float cy = py + d[1]*ph;
    float w  = pw * expf(d[2]);
    float h  = ph * expf(d[3]);
    float Hc = (float)img_sizes[b*2 + 0];
    float Wc = (float)img_sizes[b*2 + 1];
    float bx1 = fminf(fmaxf(cx - w*0.5f, 0.0f), Wc);
    float by1 = fminf(fmaxf(cy - h*0.5f, 0.0f), Hc);
    float bx2 = fminf(fmaxf(cx + w*0.5f, 0.0f), Wc);
    float by2 = fminf(fmaxf(cy + h*0.5f, 0.0f), Hc);

    float score = g_probs[roi*NUM_CLASSES + cls];
    int flat = r*(NUM_CLASSES-1) + c;
    int g = b*NCAND + flat;
    g_fb[g*4+0] = bx1; g_fb[g*4+1] = by1; g_fb[g*4+2] = bx2; g_fb[g*4+3] = by2;
    g_fs[g] = score;
    g_valid[g] = (score > SCORE_THRESH) ? 1 : 0;
    g_kept[g] = 0;
}

// ---------------- 8. per-class NMS ----------------
__global__ void k_nms() {
    int b = blockIdx.x / (NUM_CLASSES-1);
    int c = blockIdx.x % (NUM_CLASSES-1);
    int tid = threadIdx.x;

    __shared__ unsigned long long key[NPROP];
    __shared__ float bx1[NPROP], by1[NPROP], bx2[NPROP], by2[NPROP], ar[NPROP];
    __shared__ unsigned char keep[NPROP];

    int flat = tid*(NUM_CLASSES-1) + c;
    int g = b*NCAND + flat;
    float s = g_fs[g];
    bool v = g_valid[g] != 0;
    key[tid] = v ? ((((unsigned long long)flip_f32(s)) << 32) |
                   (unsigned long long)(0xFFFFFFFFu - (unsigned)flat)) : 0ull;

    for (int k = 2; k <= NPROP; k <<= 1) {
        for (int j = k >> 1; j > 0; j >>= 1) {
            __syncthreads();
            int ixj = tid ^ j;
            if (ixj > tid) {
                unsigned long long a = key[tid], bb_ = key[ixj];
                bool sw = ((tid & k) == 0) ? (a < bb_) : (a > bb_);
                if (sw) { key[tid] = bb_; key[ixj] = a; }
            }
        }
    }
    __syncthreads();

    unsigned long long kk = key[tid];
    bool vj = kk != 0ull;
    int sflat = -1;
    if (vj) {
        sflat = (int)(0xFFFFFFFFu - (unsigned)(kk & 0xFFFFFFFFu));
        const float* bp = g_fb + (b*NCAND + sflat)*4;
        bx1[tid] = bp[0]; by1[tid] = bp[1]; bx2[tid] = bp[2]; by2[tid] = bp[3];
        ar[tid] = (bp[2]-bp[0]) * (bp[3]-bp[1]);
    }
    keep[tid] = vj ? 1 : 0;
    int nv = __syncthreads_count(vj ? 1 : 0);

    for (int i = 0; i < nv; i++) {
        __syncthreads();
        if (!keep[i]) continue;
        if (tid > i && keep[tid]) {
            float xi1 = fmaxf(bx1[i], bx1[tid]);
            float yi1 = fmaxf(by1[i], by1[tid]);
            float xi2 = fminf(bx2[i], bx2[tid]);
            float yi2 = fminf(by2[i], by2[tid]);
            float inter = fmaxf(xi2 - xi1, 0.0f) * fmaxf(yi2 - yi1, 0.0f);
            float iou = inter / (ar[i] + ar[tid] - inter + 1e-9f);
            if (iou > NMS_THRESH) keep[tid] = 0;
        }
    }
    __syncthreads();
    if (vj && keep[tid]) g_kept[b*NCAND + sflat] = 1;
}

// ---------------- 9. final top-100 ----------------
__global__ __launch_bounds__(1024)
void k_final(float* __restrict__ out) {
    int b = blockIdx.x;
    int tid = threadIdx.x;
    __shared__ unsigned long long key[4096];

    for (int i = tid; i < 4096; i += 1024) {
        unsigned long long k = 0ull;
        if (i < NCAND && g_kept[b*NCAND + i]) {
            float s = g_fs[b*NCAND + i];
            k = (((unsigned long long)flip_f32(s)) << 32) |
                (unsigned long long)(0xFFFFFFFFu - (unsigned)i);
        }
        key[i] = k;
    }
    for (int k = 2; k <= 4096; k <<= 1) {
        for (int j = k >> 1; j > 0; j >>= 1) {
            __syncthreads();
            for (int i = tid; i < 4096; i += 1024) {
                int ixj = i ^ j;
                if (ixj > i) {
                    unsigned long long a = key[i], bb_ = key[ixj];
                    bool sw = ((i & k) == 0) ? (a < bb_) : (a > bb_);
                    if (sw) { key[i] = bb_; key[ixj] = a; }
                }
            }
        }
    }
    __syncthreads();

    if (tid < MAX_DET) {
        unsigned long long k = key[tid];
        float b0=0,b1=0,b2=0,b3=0, sc=0, lb=0;
        if (k != 0ull) {
            int flat = (int)(0xFFFFFFFFu - (unsigned)(k & 0xFFFFFFFFu));
            const float* bp = g_fb + (b*NCAND + flat)*4;
            b0 = bp[0]; b1 = bp[1]; b2 = bp[2]; b3 = bp[3];
            sc = g_fs[b*NCAND + flat];
            lb = (float)(flat % (NUM_CLASSES-1) + 1);
        }
        out[b*MAX_DET*4 + tid*4 + 0] = b0;
        out[b*MAX_DET*4 + tid*4 + 1] = b1;
        out[b*MAX_DET*4 + tid*4 + 2] = b2;
        out[b*MAX_DET*4 + tid*4 + 3] = b3;
        out[BATCH*MAX_DET*4 + b*MAX_DET + tid] = sc;
        out[BATCH*MAX_DET*4 + BATCH*MAX_DET + b*MAX_DET + tid] = lb;
    }
}

__global__ void k_zero(float* o, int n) {
    int i = blockIdx.x * blockDim.x + threadIdx.x;
    if (i < n) o[i] = 0.0f;
}

// ---------------- launch ----------------
extern "C" void kernel_launch(void* const* d_in, const int* in_sizes, int n_in,
                              void* d_out, int out_size) {
    const float* features  = (const float*)d_in[0];
    const float* proposals = (const float*)d_in[1];
    const int*   img_sizes = (const int*)  d_in[2];
    const float* W1 = (const float*)d_in[3];
    const float* b1 = (const float*)d_in[4];
    const float* W2 = (const float*)d_in[5];
    const float* b2 = (const float*)d_in[6];
    const float* Wc = (const float*)d_in[7];
    const float* bc = (const float*)d_in[8];
    const float* Wb = (const float*)d_in[9];
    const float* bb = (const float*)d_in[10];
    float* out = (float*)d_out;

    float *pX, *pPart, *pH1, *pH2;
    cudaGetSymbolAddress((void**)&pX,    g_X);
    cudaGetSymbolAddress((void**)&pPart, g_part);
    cudaGetSymbolAddress((void**)&pH1,   g_H1);
    cudaGetSymbolAddress((void**)&pH2,   g_H2);

    cudaFuncSetAttribute(k_gemm_mma, cudaFuncAttributeMaxDynamicSharedMemorySize, SMEM_GEMM);

    k_zero<<<(out_size + 255)/256, 256>>>(out, out_size);

    k_transpose<<<dim3(32, 8, BATCH), dim3(32, 8)>>>(features);
    k_roialign<<<NROI, IN_CH>>>(proposals);

    // FC1: M=256 (2 tiles of 128), N=1024 (4 tiles of 256), splitK=16
    k_gemm_mma<<<dim3(2, 4, SPLITK), 256, SMEM_GEMM>>>(pX, W1, pPart, FEAT_DIM);
    k_reduce_bias_relu<<<(NROI*HID)/256, 256>>>(pPart, b1, pH1);
    // FC2
    k_gemm_mma<<<dim3(2, 4, SPLITK), 256, SMEM_GEMM>>>(pH1, W2, pPart, HID);
    k_reduce_bias_relu<<<(NROI*HID)/256, 256>>>(pPart, b2, pH2);

    k_heads<<<NROI, 128>>>(Wc, bc, Wb, bb);
    k_softmax<<<1, NROI>>>();
    k_decode<<<(BATCH*NCAND + 255)/256, 256>>>(proposals, img_sizes);
    k_nms<<<BATCH*(NUM_CLASSES-1), NPROP>>>();
    k_final<<<BATCH, 1024>>>(out);
}

// round 5
// speedup vs baseline: 1.2932x; 1.0318x over previous
#include <cuda_runtime.h>
#include <cstdint>
#include <math.h>

// ---------------- problem constants ----------------
#define BATCH 2
#define NPROP 128
#define NROI 256
#define IN_CH 256
#define FH 32
#define FW 32
#define ROI 7
#define FEAT_DIM 12544
#define HID 1024
#define NUM_CLASSES 21
#define NCAND 2560
#define MAX_DET 100
#define SPATIAL_SCALE (1.0f/32.0f)
#define SCORE_THRESH 0.05f
#define NMS_THRESH 0.5f
#define SPLITK 16

// ---------------- scratch ----------------
__device__ float g_featT[BATCH*FH*FW*IN_CH];
__device__ float g_X[NROI*FEAT_DIM];
__device__ float g_part[SPLITK*NROI*HID];
__device__ float g_H1[NROI*HID];
__device__ float g_H2[NROI*HID];
__device__ float g_fb[BATCH*NCAND*4];
__device__ float g_fs[BATCH*NCAND];
__device__ unsigned char g_valid[BATCH*NCAND];
__device__ unsigned char g_kept[BATCH*NCAND];

// ---------------- helpers ----------------
__device__ __forceinline__ uint32_t smem_u32(const void* p) {
    uint32_t a;
    asm("{ .reg .u64 t; cvta.to.shared.u64 t, %1; cvt.u32.u64 %0, t; }" : "=r"(a) : "l"(p));
    return a;
}
__device__ __forceinline__ unsigned int flip_f32(float f) {
    unsigned int u = __float_as_uint(f);
    return (u & 0x80000000u) ? ~u : (u | 0x80000000u);
}
__device__ __forceinline__ void splitf(float v, uint32_t& hi, uint32_t& lo) {
    uint32_t h = __float_as_uint(v) & 0xFFFFE000u;
    hi = h;
    lo = __float_as_uint(v - __uint_as_float(h));
}
__device__ __forceinline__ void mma8(float* d, const uint32_t* a, const uint32_t* b) {
    asm volatile(
        "mma.sync.aligned.m16n8k8.row.col.f32.tf32.tf32.f32 "
        "{%0,%1,%2,%3}, {%4,%5,%6,%7}, {%8,%9}, {%0,%1,%2,%3};"
        : "+f"(d[0]), "+f"(d[1]), "+f"(d[2]), "+f"(d[3])
        : "r"(a[0]), "r"(a[1]), "r"(a[2]), "r"(a[3]), "r"(b[0]), "r"(b[1]));
}
__device__ __forceinline__ void cp16(uint32_t sdst, const float* gsrc) {
    asm volatile("cp.async.cg.shared.global [%0], [%1], 16;" :: "r"(sdst), "l"(gsrc));
}

// ---------------- 1. feature transpose NCHW -> NHWC ----------------
__global__ void k_transpose(const float* __restrict__ f) {
    __shared__ float t[32][33];
    int b  = blockIdx.z;
    int c0 = blockIdx.y * 32;
    int w0 = blockIdx.x * 32;
    int tx = threadIdx.x, ty = threadIdx.y;
    #pragma unroll
    for (int i = ty; i < 32; i += 8)
        t[i][tx] = f[(b*IN_CH + c0 + i)*1024 + w0 + tx];
    __syncthreads();
    #pragma unroll
    for (int i = ty; i < 32; i += 8)
        g_featT[(b*1024 + w0 + i)*IN_CH + c0 + tx] = t[tx][i];
}

// ---------------- 2. RoIAlign (SMEM window + precomputed geometry) ----------------
// Sample footprint per RoI is <= 8x8 feature cells (rw,rh <= 5 cells).
#define WIN 8
#define NSAMP 196      // 49 bins * 4 samples
__global__ __launch_bounds__(256)
void k_roialign(const float* __restrict__ proposals) {
    __shared__ float win[WIN*WIN*IN_CH];            // 64 KB
    __shared__ float gw00[NSAMP], gw01[NSAMP], gw10[NSAMP], gw11[NSAMP];
    __shared__ int   gi00[NSAMP], gi01[NSAMP], gi10[NSAMP], gi11[NSAMP];

    int n = blockIdx.x;
    int b = n >> 7;
    int tid = threadIdx.x;

    const float* p = proposals + n*4;
    float x1 = p[0]*SPATIAL_SCALE, y1 = p[1]*SPATIAL_SCALE;
    float x2 = p[2]*SPATIAL_SCALE, y2 = p[3]*SPATIAL_SCALE;
    float rw = fmaxf(x2 - x1, 1.0f), rh = fmaxf(y2 - y1, 1.0f);
    float bw = rw / (float)ROI, bh = rh / (float)ROI;

    float ycmin = fminf(fmaxf(y1 + 0.25f*bh, 0.0f), (float)(FH-1));
    float xcmin = fminf(fmaxf(x1 + 0.25f*bw, 0.0f), (float)(FW-1));
    int y0w = (int)floorf(ycmin);
    int x0w = (int)floorf(xcmin);

    // geometry precompute: one thread per (bin, sample)
    if (tid < NSAMP) {
        int bin = tid >> 2, s = tid & 3;
        int ph = bin / ROI, pw_ = bin - ph*ROI;
        int sy = s >> 1, sx = s & 1;
        float gy = (float)ph  + ((float)sy + 0.5f) * 0.5f;
        float gx = (float)pw_ + ((float)sx + 0.5f) * 0.5f;
        float yc = fminf(fmaxf(y1 + gy*bh, 0.0f), (float)(FH-1));
        float xc = fminf(fmaxf(x1 + gx*bw, 0.0f), (float)(FW-1));
        float y0f = floorf(yc), x0f = floorf(xc);
        int y0 = (int)y0f, x0 = (int)x0f;
        int y1i = min(y0 + 1, FH-1), x1i = min(x0 + 1, FW-1);
        float ly = yc - y0f, lx = xc - x0f;
        float hy = 1.0f - ly, hx = 1.0f - lx;
        int iy0 = y0 - y0w,  iy1 = y1i - y0w;
        int jx0 = x0 - x0w,  jx1 = x1i - x0w;
        gw00[tid] = hy*hx*0.25f; gw01[tid] = hy*lx*0.25f;
        gw10[tid] = ly*hx*0.25f; gw11[tid] = ly*lx*0.25f;
        gi00[tid] = (iy0*WIN + jx0)*IN_CH;
        gi01[tid] = (iy0*WIN + jx1)*IN_CH;
        gi10[tid] = (iy1*WIN + jx0)*IN_CH;
        gi11[tid] = (iy1*WIN + jx1)*IN_CH;
    }

    // window load: 64 cells, 4 threads per cell, 16 float4 each
    {
        int cell = tid >> 2, cq = tid & 3;
        int iy = cell >> 3, jx = cell & 7;
        int fy = min(y0w + iy, FH-1), fx = min(x0w + jx, FW-1);
        const float4* src = (const float4*)&g_featT[(((b*FH + fy)*FW) + fx)*IN_CH];
        float4* dst = (float4*)&win[cell*IN_CH];
        #pragma unroll
        for (int q = 0; q < 16; q++)
            dst[cq*16 + q] = src[cq*16 + q];
    }
    __syncthreads();

    int c = tid;
    float* outp = &g_X[(size_t)n*FEAT_DIM + c*(ROI*ROI)];
    #pragma unroll 7
    for (int bin = 0; bin < ROI*ROI; bin++) {
        float acc = 0.0f;
        #pragma unroll
        for (int s = 0; s < 4; s++) {
            int g = bin*4 + s;
            acc += gw00[g]*win[gi00[g] + c] + gw01[g]*win[gi01[g] + c]
                 + gw10[g]*win[gi10[g] + c] + gw11[g]*win[gi11[g] + c];
        }
        outp[bin] = acc;
    }
}

// ---------------- 3. tf32x3 mma.sync GEMM (3-stage, fragment-pipelined) ----------------
#define ASTR 36
#define WSTR 36
#define A_FLOATS (128*ASTR)
#define W_FLOATS (256*WSTR)
#define STAGE_FLOATS (A_FLOATS + W_FLOATS)
#define SMEM_GEMM (3*STAGE_FLOATS*4)

__global__ __launch_bounds__(256, 1)
void k_gemm_mma(const float* __restrict__ A, const float* __restrict__ W,
                float* __restrict__ Cp, int K) {
    extern __shared__ float sm[];
    const uint32_t smb = smem_u32(sm);
    int tid = threadIdx.x;
    int wid = tid >> 5, lane = tid & 31;
    int wm = wid >> 2, wn = wid & 3;
    int m0 = blockIdx.x * 128;
    int n0 = blockIdx.y * 256;
    int z = blockIdx.z, Z = gridDim.z;
    int KT = K >> 5;
    int ntiles = (KT - z + Z - 1) / Z;

    float acc[4][8][4];
    #pragma unroll
    for (int i = 0; i < 4; i++)
        #pragma unroll
        for (int j = 0; j < 8; j++)
            #pragma unroll
            for (int q = 0; q < 4; q++) acc[i][j][q] = 0.0f;

    auto issue = [&](int ti) {
        int kt = z + ti * Z;
        uint32_t sa = smb + (uint32_t)((ti % 3) * STAGE_FLOATS) * 4u;
        uint32_t sw = sa + A_FLOATS * 4u;
        #pragma unroll
        for (int r = 0; r < 4; r++) {
            int t = tid + r*256;
            int row = t >> 3, q = t & 7;
            cp16(sa + (uint32_t)(row*ASTR + q*4)*4u,
                 &A[(size_t)(m0+row)*K + kt*32 + q*4]);
        }
        #pragma unroll
        for (int r = 0; r < 8; r++) {
            int t = tid + r*256;
            int row = t >> 3, q = t & 7;
            cp16(sw + (uint32_t)(row*WSTR + q*4)*4u,
                 &W[(size_t)(n0+row)*K + kt*32 + q*4]);
        }
        asm volatile("cp.async.commit_group;" ::: "memory");
    };

    issue(0);
    if (ntiles > 1) issue(1);

    for (int t = 0; t < ntiles; t++) {
        if (t + 1 < ntiles) asm volatile("cp.async.wait_group 1;" ::: "memory");
        else                asm volatile("cp.async.wait_group 0;" ::: "memory");
        __syncthreads();
        if (t + 2 < ntiles) issue(t + 2);

        const float* As = sm + (t % 3) * STAGE_FLOATS;
        const float* Ws = As + A_FLOATS;

        float araw[16], wraw[16];
        {
            int kc = lane & 3;
            #pragma unroll
            for (int mt = 0; mt < 4; mt++) {
                int r = wm*64 + mt*16 + (lane >> 2);
                araw[mt*4+0] = As[r*ASTR + kc];
                araw[mt*4+1] = As[(r+8)*ASTR + kc];
                araw[mt*4+2] = As[r*ASTR + kc + 4];
                araw[mt*4+3] = As[(r+8)*ASTR + kc + 4];
            }
            #pragma unroll
            for (int nt = 0; nt < 8; nt++) {
                int nr = wn*64 + nt*8 + (lane >> 2);
                wraw[nt*2+0] = Ws[nr*WSTR + kc];
                wraw[nt*2+1] = Ws[nr*WSTR + kc + 4];
            }
        }

        #pragma unroll
        for (int ks = 0; ks < 4; ks++) {
            uint32_t aH[4][4], aL[4][4], wH[8][2], wL[8][2];
            #pragma unroll
            for (int i = 0; i < 16; i++)
                splitf(araw[i], aH[i>>2][i&3], aL[i>>2][i&3]);
            #pragma unroll
            for (int i = 0; i < 16; i++)
                splitf(wraw[i], wH[i>>1][i&1], wL[i>>1][i&1]);

            // prefetch next ks fragments (hidden behind the 96 MMAs below)
            if (ks < 3) {
                int kc = (ks+1)*8 + (lane & 3);
                #pragma unroll
                for (int mt = 0; mt < 4; mt++) {
                    int r = wm*64 + mt*16 + (lane >> 2);
                    araw[mt*4+0] = As[r*ASTR + kc];
                    araw[mt*4+1] = As[(r+8)*ASTR + kc];
                    araw[mt*4+2] = As[r*ASTR + kc + 4];
                    araw[mt*4+3] = As[(r+8)*ASTR + kc + 4];
                }
                #pragma unroll
                for (int nt = 0; nt < 8; nt++) {
                    int nr = wn*64 + nt*8 + (lane >> 2);
                    wraw[nt*2+0] = Ws[nr*WSTR + kc];
                    wraw[nt*2+1] = Ws[nr*WSTR + kc + 4];
                }
            }

            #pragma unroll
            for (int mt = 0; mt < 4; mt++)
                #pragma unroll
                for (int nt = 0; nt < 8; nt++) {
                    mma8(acc[mt][nt], aH[mt], wH[nt]);
                    mma8(acc[mt][nt], aL[mt], wH[nt]);
                    mma8(acc[mt][nt], aH[mt], wL[nt]);
                }
        }
    }

    float* C = Cp + (size_t)z * (NROI*HID);
    #pragma unroll
    for (int mt = 0; mt < 4; mt++) {
        int r = m0 + wm*64 + mt*16 + (lane >> 2);
        #pragma unroll
        for (int nt = 0; nt < 8; nt++) {
            int c = n0 + wn*64 + nt*8 + (lane & 3)*2;
            *(float2*)&C[(size_t)r*HID + c]     = make_float2(acc[mt][nt][0], acc[mt][nt][1]);
            *(float2*)&C[(size_t)(r+8)*HID + c] = make_float2(acc[mt][nt][2], acc[mt][nt][3]);
        }
    }
}

// ---------------- 4. split-K reduce + bias + relu (vectorized) ----------------
__global__ void k_reduce_bias_relu(const float* __restrict__ Cp,
                                   const float* __restrict__ bias,
                                   float* __restrict__ out) {
    int i = (blockIdx.x * blockDim.x + threadIdx.x) * 4;
    float4 s = make_float4(0.f, 0.f, 0.f, 0.f);
    #pragma unroll
    for (int k = 0; k < SPLITK; k++) {
        float4 v = *(const float4*)&Cp[(size_t)k*(NROI*HID) + i];
        s.x += v.x; s.y += v.y; s.z += v.z; s.w += v.w;
    }
    float4 bv = *(const float4*)&bias[i & (HID-1)];
    float4 o;
    o.x = fmaxf(s.x + bv.x, 0.f); o.y = fmaxf(s.y + bv.y, 0.f);
    o.z = fmaxf(s.z + bv.z, 0.f); o.w = fmaxf(s.w + bv.w, 0.f);
    *(float4*)&out[i] = o;
}

// ---------------- 5. fused heads + softmax + decode ----------------
__global__ __launch_bounds__(128)
void k_head_post(const float* __restrict__ Wc, const float* __restrict__ bc,
                 const float* __restrict__ Wb, const float* __restrict__ bb,
                 const float* __restrict__ proposals,
                 const int* __restrict__ img_sizes) {
    int roi = blockIdx.x;
    int b = roi >> 7, r = roi & 127;
    int tid = threadIdx.x;
    __shared__ float xs[HID];
    __shared__ float lg[NUM_CLASSES];
    __shared__ float rg[NUM_CLASSES*4];

    #pragma unroll
    for (int q = 0; q < 2; q++) {
        int e = (tid + q*128) * 4;
        *(float4*)&xs[e] = *(const float4*)&g_H2[(size_t)roi*HID + e];
    }
    __syncthreads();

    int warp = tid >> 5, lane = tid & 31;
    for (int o = warp; o < NUM_CLASSES*5; o += 4) {
        const float* Wrow; float bias;
        if (o < NUM_CLASSES) { Wrow = Wc + o*HID; bias = bc[o]; }
        else { Wrow = Wb + (o - NUM_CLASSES)*HID; bias = bb[o - NUM_CLASSES]; }
        float s = 0.0f;
        #pragma unroll 8
        for (int k = lane; k < HID; k += 32) s = fmaf(Wrow[k], xs[k], s);
        #pragma unroll
        for (int off = 16; off; off >>= 1) s += __shfl_down_sync(0xffffffffu, s, off);
        if (lane == 0) {
            s += bias;
            if (o < NUM_CLASSES) lg[o] = s;
            else rg[o - NUM_CLASSES] = s;
        }
    }
    __syncthreads();

    if (warp == 0) {
        float v = (lane < NUM_CLASSES) ? lg[lane] : -INFINITY;
        float m = v;
        #pragma unroll
        for (int off = 16; off; off >>= 1) m = fmaxf(m, __shfl_xor_sync(0xffffffffu, m, off));
        float e = (lane < NUM_CLASSES) ? expf(v - m) : 0.0f;
        float sum = e;
        #pragma unroll
        for (int off = 16; off; off >>= 1) sum += __shfl_xor_sync(0xffffffffu, sum, off);
        float prob = e / sum;
        float prob_next = __shfl_sync(0xffffffffu, prob, (lane + 1) & 31);   // prob of class lane+1

        if (lane < NUM_CLASSES-1) {
            int c = lane, cls = c + 1;
            const float* p = proposals + roi*4;
            float pw = p[2] - p[0], ph = p[3] - p[1];
            float px = p[0] + pw*0.5f, py = p[1] + ph*0.5f;
            float d0 = rg[cls*4+0], d1 = rg[cls*4+1], d2 = rg[cls*4+2], d3 = rg[cls*4+3];
            float cx = px + d0*pw;
            float cy = py + d1*ph;
            float w  = pw * expf(d2);
            float h  = ph * expf(d3);
            float Hc = (float)img_sizes[b*2 + 0];
            float Wd = (float)img_sizes[b*2 + 1];
            float bx1 = fminf(fmaxf(cx - w*0.5f, 0.0f), Wd);
            float by1 = fminf(fmaxf(cy - h*0.5f, 0.0f), Hc);
            float bx2 = fminf(fmaxf(cx + w*0.5f, 0.0f), Wd);
            float by2 = fminf(fmaxf(cy + h*0.5f, 0.0f), Hc);
            int g = b*NCAND + r*(NUM_CLASSES-1) + c;
            g_fb[g*4+0] = bx1; g_fb[g*4+1] = by1; g_fb[g*4+2] = bx2; g_fb[g*4+3] = by2;
            g_fs[g] = prob_next;
            g_valid[g] = (prob_next > SCORE_THRESH) ? 1 : 0;
            g_kept[g] = 0;
        }
    }
}

// ---------------- 6. per-class NMS ----------------
__global__ void k_nms() {
    int b = blockIdx.x / (NUM_CLASSES-1);
    int c = blockIdx.x % (NUM_CLASSES-1);
    int tid = threadIdx.x;

    __shared__ unsigned long long key[NPROP];
    __shared__ float bx1[NPROP], by1[NPROP], bx2[NPROP], by2[NPROP], ar[NPROP];
    __shared__ unsigned char keep[NPROP];

    int flat = tid*(NUM_CLASSES-1) + c;
    int g = b*NCAND + flat;
    float s = g_fs[g];
    bool v = g_valid[g] != 0;
    key[tid] = v ? ((((unsigned long long)flip_f32(s)) << 32) |
                   (unsigned long long)(0xFFFFFFFFu - (unsigned)flat)) : 0ull;

    for (int k = 2; k <= NPROP; k <<= 1) {
        for (int j = k >> 1; j > 0; j >>= 1) {
            __syncthreads();
            int ixj = tid ^ j;
            if (ixj > tid) {
                unsigned long long a = key[tid], bb_ = key[ixj];
                bool sw = ((tid & k) == 0) ? (a < bb_) : (a > bb_);
                if (sw) { key[tid] = bb_; key[ixj] = a; }
            }
        }
    }
    __syncthreads();

    unsigned long long kk = key[tid];
    bool vj = kk != 0ull;
    int sflat = -1;
    if (vj) {
        sflat = (int)(0xFFFFFFFFu - (unsigned)(kk & 0xFFFFFFFFu));
        const float* bp = g_fb + (b*NCAND + sflat)*4;
        bx1[tid] = bp[0]; by1[tid] = bp[1]; bx2[tid] = bp[2]; by2[tid] = bp[3];
        ar[tid] = (bp[2]-bp[0]) * (bp[3]-bp[1]);
    }
    keep[tid] = vj ? 1 : 0;
    int nv = __syncthreads_count(vj ? 1 : 0);

    for (int i = 0; i < nv; i++) {
        __syncthreads();
        if (!keep[i]) continue;
        if (tid > i && keep[tid]) {
            float xi1 = fmaxf(bx1[i], bx1[tid]);
            float yi1 = fmaxf(by1[i], by1[tid]);
            float xi2 = fminf(bx2[i], bx2[tid]);
            float yi2 = fminf(by2[i], by2[tid]);
            float inter = fmaxf(xi2 - xi1, 0.0f) * fmaxf(yi2 - yi1, 0.0f);
            float iou = inter / (ar[i] + ar[tid] - inter + 1e-9f);
            if (iou > NMS_THRESH) keep[tid] = 0;
        }
    }
    __syncthreads();
    if (vj && keep[tid]) g_kept[b*NCAND + sflat] = 1;
}

// ---------------- 7. final top-100 ----------------
__global__ __launch_bounds__(1024)
void k_final(float* __restrict__ out) {
    int b = blockIdx.x;
    int tid = threadIdx.x;
    __shared__ unsigned long long key[4096];

    for (int i = tid; i < 4096; i += 1024) {
        unsigned long long k = 0ull;
        if (i < NCAND && g_kept[b*NCAND + i]) {
            float s = g_fs[b*NCAND + i];
            k = (((unsigned long long)flip_f32(s)) << 32) |
                (unsigned long long)(0xFFFFFFFFu - (unsigned)i);
        }
        key[i] = k;
    }
    for (int k = 2; k <= 4096; k <<= 1) {
        for (int j = k >> 1; j > 0; j >>= 1) {
            __syncthreads();
            for (int i = tid; i < 4096; i += 1024) {
                int ixj = i ^ j;
                if (ixj > i) {
                    unsigned long long a = key[i], bb_ = key[ixj];
                    bool sw = ((i & k) == 0) ? (a < bb_) : (a > bb_);
                    if (sw) { key[i] = bb_; key[ixj] = a; }
                }
            }
        }
    }
    __syncthreads();

    if (tid < MAX_DET) {
        unsigned long long k = key[tid];
        float b0=0,b1=0,b2=0,b3=0, sc=0, lb=0;
        if (k != 0ull) {
            int flat = (int)(0xFFFFFFFFu - (unsigned)(k & 0xFFFFFFFFu));
            const float* bp = g_fb + (b*NCAND + flat)*4;
            b0 = bp[0]; b1 = bp[1]; b2 = bp[2]; b3 = bp[3];
            sc = g_fs[b*NCAND + flat];
            lb = (float)(flat % (NUM_CLASSES-1) + 1);
        }
        out[b*MAX_DET*4 + tid*4 + 0] = b0;
        out[b*MAX_DET*4 + tid*4 + 1] = b1;
        out[b*MAX_DET*4 + tid*4 + 2] = b2;
        out[b*MAX_DET*4 + tid*4 + 3] = b3;
        out[BATCH*MAX_DET*4 + b*MAX_DET + tid] = sc;
        out[BATCH*MAX_DET*4 + BATCH*MAX_DET + b*MAX_DET + tid] = lb;
    }
}

// ---------------- launch ----------------
extern "C" void kernel_launch(void* const* d_in, const int* in_sizes, int n_in,
                              void* d_out, int out_size) {
    const float* features  = (const float*)d_in[0];
    const float* proposals = (const float*)d_in[1];
    const int*   img_sizes = (const int*)  d_in[2];
    const float* W1 = (const float*)d_in[3];
    const float* b1 = (const float*)d_in[4];
    const float* W2 = (const float*)d_in[5];
    const float* b2 = (const float*)d_in[6];
    const float* Wc = (const float*)d_in[7];
    const float* bc = (const float*)d_in[8];
    const float* Wb = (const float*)d_in[9];
    const float* bb = (const float*)d_in[10];
    float* out = (float*)d_out;

    float *pX, *pPart, *pH1, *pH2;
    cudaGetSymbolAddress((void**)&pX,    g_X);
    cudaGetSymbolAddress((void**)&pPart, g_part);
    cudaGetSymbolAddress((void**)&pH1,   g_H1);
    cudaGetSymbolAddress((void**)&pH2,   g_H2);

    cudaFuncSetAttribute(k_gemm_mma, cudaFuncAttributeMaxDynamicSharedMemorySize, SMEM_GEMM);

    k_transpose<<<dim3(32, 8, BATCH), dim3(32, 8)>>>(features);
    k_roialign<<<NROI, 256>>>(proposals);

    k_gemm_mma<<<dim3(2, 4, SPLITK), 256, SMEM_GEMM>>>(pX, W1, pPart, FEAT_DIM);
    k_reduce_bias_relu<<<(NROI*HID)/1024, 256>>>(pPart, b1, pH1);
    k_gemm_mma<<<dim3(2, 4, SPLITK), 256, SMEM_GEMM>>>(pH1, W2, pPart, HID);
    k_reduce_bias_relu<<<(NROI*HID)/1024, 256>>>(pPart, b2, pH2);

    k_head_post<<<NROI, 128>>>(Wc, bc, Wb, bb, proposals, img_sizes);
    k_nms<<<BATCH*(NUM_CLASSES-1), NPROP>>>();
    k_final<<<BATCH, 1024>>>(out);
}

// round 6
// speedup vs baseline: 1.6111x; 1.2458x over previous
#include <cuda_runtime.h>
#include <cstdint>
#include <math.h>

// ---------------- problem constants ----------------
#define BATCH 2
#define NPROP 128
#define NROI 256
#define IN_CH 256
#define FH 32
#define FW 32
#define ROI 7
#define FEAT_DIM 12544
#define HID 1024
#define NUM_CLASSES 21
#define NCAND 2560
#define MAX_DET 100
#define SPATIAL_SCALE (1.0f/32.0f)
#define SCORE_THRESH 0.05f
#define NMS_THRESH 0.5f
#define SPLITK 16

// ---------------- scratch ----------------
__device__ float g_featT[BATCH*FH*FW*IN_CH];
__device__ float g_X[NROI*FEAT_DIM];
__device__ float g_part[SPLITK*NROI*HID];
__device__ float g_H1[NROI*HID];
__device__ float g_H2[NROI*HID];
__device__ float g_fb[BATCH*NCAND*4];
__device__ float g_fs[BATCH*NCAND];
__device__ unsigned char g_valid[BATCH*NCAND];
__device__ unsigned char g_kept[BATCH*NCAND];

// ---------------- helpers ----------------
__device__ __forceinline__ uint32_t smem_u32(const void* p) {
    uint32_t a;
    asm("{ .reg .u64 t; cvta.to.shared.u64 t, %1; cvt.u32.u64 %0, t; }" : "=r"(a) : "l"(p));
    return a;
}
__device__ __forceinline__ unsigned int flip_f32(float f) {
    unsigned int u = __float_as_uint(f);
    return (u & 0x80000000u) ? ~u : (u | 0x80000000u);
}
__device__ __forceinline__ void splitf(float v, uint32_t& hi, uint32_t& lo) {
    uint32_t h = __float_as_uint(v) & 0xFFFFE000u;
    hi = h;
    lo = __float_as_uint(v - __uint_as_float(h));
}
__device__ __forceinline__ void mma8(float* d, const uint32_t* a, const uint32_t* b) {
    asm volatile(
        "mma.sync.aligned.m16n8k8.row.col.f32.tf32.tf32.f32 "
        "{%0,%1,%2,%3}, {%4,%5,%6,%7}, {%8,%9}, {%0,%1,%2,%3};"
        : "+f"(d[0]), "+f"(d[1]), "+f"(d[2]), "+f"(d[3])
        : "r"(a[0]), "r"(a[1]), "r"(a[2]), "r"(a[3]), "r"(b[0]), "r"(b[1]));
}
__device__ __forceinline__ void cp16(uint32_t sdst, const float* gsrc) {
    asm volatile("cp.async.cg.shared.global [%0], [%1], 16;" :: "r"(sdst), "l"(gsrc));
}

// ---------------- 1. feature transpose NCHW -> NHWC ----------------
__global__ void k_transpose(const float* __restrict__ f) {
    __shared__ float t[32][33];
    int b  = blockIdx.z;
    int c0 = blockIdx.y * 32;
    int w0 = blockIdx.x * 32;
    int tx = threadIdx.x, ty = threadIdx.y;
    #pragma unroll
    for (int i = ty; i < 32; i += 8)
        t[i][tx] = f[(b*IN_CH + c0 + i)*1024 + w0 + tx];
    __syncthreads();
    #pragma unroll
    for (int i = ty; i < 32; i += 8)
        g_featT[(b*1024 + w0 + i)*IN_CH + c0 + tx] = t[tx][i];
}

// ---------------- 2. RoIAlign (SMEM window + precomputed geometry) ----------------
#define WIN 8
#define NSAMP 196
__global__ __launch_bounds__(256)
void k_roialign(const float* __restrict__ proposals) {
    __shared__ float win[WIN*WIN*IN_CH];
    __shared__ float gw00[NSAMP], gw01[NSAMP], gw10[NSAMP], gw11[NSAMP];
    __shared__ int   gi00[NSAMP], gi01[NSAMP], gi10[NSAMP], gi11[NSAMP];

    int n = blockIdx.x;
    int b = n >> 7;
    int tid = threadIdx.x;

    const float* p = proposals + n*4;
    float x1 = p[0]*SPATIAL_SCALE, y1 = p[1]*SPATIAL_SCALE;
    float x2 = p[2]*SPATIAL_SCALE, y2 = p[3]*SPATIAL_SCALE;
    float rw = fmaxf(x2 - x1, 1.0f), rh = fmaxf(y2 - y1, 1.0f);
    float bw = rw / (float)ROI, bh = rh / (float)ROI;

    float ycmin = fminf(fmaxf(y1 + 0.25f*bh, 0.0f), (float)(FH-1));
    float xcmin = fminf(fmaxf(x1 + 0.25f*bw, 0.0f), (float)(FW-1));
    int y0w = (int)floorf(ycmin);
    int x0w = (int)floorf(xcmin);

    if (tid < NSAMP) {
        int bin = tid >> 2, s = tid & 3;
        int ph = bin / ROI, pw_ = bin - ph*ROI;
        int sy = s >> 1, sx = s & 1;
        float gy = (float)ph  + ((float)sy + 0.5f) * 0.5f;
        float gx = (float)pw_ + ((float)sx + 0.5f) * 0.5f;
        float yc = fminf(fmaxf(y1 + gy*bh, 0.0f), (float)(FH-1));
        float xc = fminf(fmaxf(x1 + gx*bw, 0.0f), (float)(FW-1));
        float y0f = floorf(yc), x0f = floorf(xc);
        int y0 = (int)y0f, x0 = (int)x0f;
        int y1i = min(y0 + 1, FH-1), x1i = min(x0 + 1, FW-1);
        float ly = yc - y0f, lx = xc - x0f;
        float hy = 1.0f - ly, hx = 1.0f - lx;
        int iy0 = y0 - y0w,  iy1 = y1i - y0w;
        int jx0 = x0 - x0w,  jx1 = x1i - x0w;
        gw00[tid] = hy*hx*0.25f; gw01[tid] = hy*lx*0.25f;
        gw10[tid] = ly*hx*0.25f; gw11[tid] = ly*lx*0.25f;
        gi00[tid] = (iy0*WIN + jx0)*IN_CH;
        gi01[tid] = (iy0*WIN + jx1)*IN_CH;
        gi10[tid] = (iy1*WIN + jx0)*IN_CH;
        gi11[tid] = (iy1*WIN + jx1)*IN_CH;
    }

    {
        int cell = tid >> 2, cq = tid & 3;
        int iy = cell >> 3, jx = cell & 7;
        int fy = min(y0w + iy, FH-1), fx = min(x0w + jx, FW-1);
        const float4* src = (const float4*)&g_featT[(((b*FH + fy)*FW) + fx)*IN_CH];
        float4* dst = (float4*)&win[cell*IN_CH];
        #pragma unroll
        for (int q = 0; q < 16; q++)
            dst[cq*16 + q] = src[cq*16 + q];
    }
    __syncthreads();

    int c = tid;
    float* outp = &g_X[(size_t)n*FEAT_DIM + c*(ROI*ROI)];
    #pragma unroll 7
    for (int bin = 0; bin < ROI*ROI; bin++) {
        float acc = 0.0f;
        #pragma unroll
        for (int s = 0; s < 4; s++) {
            int g = bin*4 + s;
            acc += gw00[g]*win[gi00[g] + c] + gw01[g]*win[gi01[g] + c]
                 + gw10[g]*win[gi10[g] + c] + gw11[g]*win[gi11[g] + c];
        }
        outp[bin] = acc;
    }
}

// ---------------- 3. tf32x3 mma.sync GEMM (3-stage ring, R3 inner loop) ----------------
#define ASTR 36
#define WSTR 36
#define A_FLOATS (128*ASTR)
#define W_FLOATS (256*WSTR)
#define STAGE_FLOATS (A_FLOATS + W_FLOATS)
#define SMEM_GEMM (3*STAGE_FLOATS*4)

__global__ __launch_bounds__(256, 1)
void k_gemm_mma(const float* __restrict__ A, const float* __restrict__ W,
                float* __restrict__ Cp, int K) {
    extern __shared__ float sm[];
    const uint32_t smb = smem_u32(sm);
    int tid = threadIdx.x;
    int wid = tid >> 5, lane = tid & 31;
    int wm = wid >> 2, wn = wid & 3;
    int m0 = blockIdx.x * 128;
    int n0 = blockIdx.y * 256;
    int z = blockIdx.z, Z = gridDim.z;
    int KT = K >> 5;
    int ntiles = (KT - z + Z - 1) / Z;

    float acc[4][8][4];
    #pragma unroll
    for (int i = 0; i < 4; i++)
        #pragma unroll
        for (int j = 0; j < 8; j++)
            #pragma unroll
            for (int q = 0; q < 4; q++) acc[i][j][q] = 0.0f;

    auto issue = [&](int ti) {
        int kt = z + ti * Z;
        uint32_t sa = smb + (uint32_t)((ti % 3) * STAGE_FLOATS) * 4u;
        uint32_t sw = sa + A_FLOATS * 4u;
        #pragma unroll
        for (int r = 0; r < 4; r++) {
            int t = tid + r*256;
            int row = t >> 3, q = t & 7;
            cp16(sa + (uint32_t)(row*ASTR + q*4)*4u,
                 &A[(size_t)(m0+row)*K + kt*32 + q*4]);
        }
        #pragma unroll
        for (int r = 0; r < 8; r++) {
            int t = tid + r*256;
            int row = t >> 3, q = t & 7;
            cp16(sw + (uint32_t)(row*WSTR + q*4)*4u,
                 &W[(size_t)(n0+row)*K + kt*32 + q*4]);
        }
        asm volatile("cp.async.commit_group;" ::: "memory");
    };

    issue(0);
    if (ntiles > 1) issue(1);

    for (int t = 0; t < ntiles; t++) {
        if (t + 1 < ntiles) asm volatile("cp.async.wait_group 1;" ::: "memory");
        else                asm volatile("cp.async.wait_group 0;" ::: "memory");
        __syncthreads();
        if (t + 2 < ntiles) issue(t + 2);

        const float* As = sm + (t % 3) * STAGE_FLOATS;
        const float* Ws = As + A_FLOATS;

        #pragma unroll
        for (int ks = 0; ks < 4; ks++) {
            int kc = ks*8 + (lane & 3);
            uint32_t aH[4][4], aL[4][4], wH[8][2], wL[8][2];
            #pragma unroll
            for (int mt = 0; mt < 4; mt++) {
                int r = wm*64 + mt*16 + (lane >> 2);
                splitf(As[r*ASTR + kc],        aH[mt][0], aL[mt][0]);
                splitf(As[(r+8)*ASTR + kc],    aH[mt][1], aL[mt][1]);
                splitf(As[r*ASTR + kc + 4],    aH[mt][2], aL[mt][2]);
                splitf(As[(r+8)*ASTR + kc + 4],aH[mt][3], aL[mt][3]);
            }
            #pragma unroll
            for (int nt = 0; nt < 8; nt++) {
                int nr = wn*64 + nt*8 + (lane >> 2);
                splitf(Ws[nr*WSTR + kc],     wH[nt][0], wL[nt][0]);
                splitf(Ws[nr*WSTR + kc + 4], wH[nt][1], wL[nt][1]);
            }
            #pragma unroll
            for (int mt = 0; mt < 4; mt++)
                #pragma unroll
                for (int nt = 0; nt < 8; nt++) {
                    mma8(acc[mt][nt], aH[mt], wH[nt]);
                    mma8(acc[mt][nt], aL[mt], wH[nt]);
                    mma8(acc[mt][nt], aH[mt], wL[nt]);
                }
        }
        __syncthreads();
    }

    float* C = Cp + (size_t)z * (NROI*HID);
    #pragma unroll
    for (int mt = 0; mt < 4; mt++) {
        int r = m0 + wm*64 + mt*16 + (lane >> 2);
        #pragma unroll
        for (int nt = 0; nt < 8; nt++) {
            int c = n0 + wn*64 + nt*8 + (lane & 3)*2;
            *(float2*)&C[(size_t)r*HID + c]     = make_float2(acc[mt][nt][0], acc[mt][nt][1]);
            *(float2*)&C[(size_t)(r+8)*HID + c] = make_float2(acc[mt][nt][2], acc[mt][nt][3]);
        }
    }
}

// ---------------- 4. split-K reduce + bias + relu ----------------
__global__ void k_reduce_bias_relu(const float* __restrict__ Cp,
                                   const float* __restrict__ bias,
                                   float* __restrict__ out) {
    int i = (blockIdx.x * blockDim.x + threadIdx.x) * 4;
    float4 s = make_float4(0.f, 0.f, 0.f, 0.f);
    #pragma unroll
    for (int k = 0; k < SPLITK; k++) {
        float4 v = *(const float4*)&Cp[(size_t)k*(NROI*HID) + i];
        s.x += v.x; s.y += v.y; s.z += v.z; s.w += v.w;
    }
    float4 bv = *(const float4*)&bias[i & (HID-1)];
    float4 o;
    o.x = fmaxf(s.x + bv.x, 0.f); o.y = fmaxf(s.y + bv.y, 0.f);
    o.z = fmaxf(s.z + bv.z, 0.f); o.w = fmaxf(s.w + bv.w, 0.f);
    *(float4*)&out[i] = o;
}

// ---------------- 5. fused heads + softmax + decode (256 threads, float4) ----------------
__global__ __launch_bounds__(256)
void k_head_post(const float* __restrict__ Wc, const float* __restrict__ bc,
                 const float* __restrict__ Wb, const float* __restrict__ bb,
                 const float* __restrict__ proposals,
                 const int* __restrict__ img_sizes) {
    int roi = blockIdx.x;
    int b = roi >> 7, r = roi & 127;
    int tid = threadIdx.x;
    __shared__ float xs[HID];
    __shared__ float lg[NUM_CLASSES];
    __shared__ float rg[NUM_CLASSES*4];

    *(float4*)&xs[tid*4] = *(const float4*)&g_H2[(size_t)roi*HID + tid*4];
    __syncthreads();

    int warp = tid >> 5, lane = tid & 31;
    for (int o = warp; o < NUM_CLASSES*5; o += 8) {
        const float* Wrow; float bias;
        if (o < NUM_CLASSES) { Wrow = Wc + o*HID; bias = bc[o]; }
        else { Wrow = Wb + (o - NUM_CLASSES)*HID; bias = bb[o - NUM_CLASSES]; }
        float s = 0.0f;
        #pragma unroll
        for (int q = 0; q < 8; q++) {
            int k = (lane + q*32) * 4;
            float4 wv = *(const float4*)&Wrow[k];
            float4 xv = *(const float4*)&xs[k];
            s += wv.x*xv.x + wv.y*xv.y + wv.z*xv.z + wv.w*xv.w;
        }
        #pragma unroll
        for (int off = 16; off; off >>= 1) s += __shfl_down_sync(0xffffffffu, s, off);
        if (lane == 0) {
            s += bias;
            if (o < NUM_CLASSES) lg[o] = s;
            else rg[o - NUM_CLASSES] = s;
        }
    }
    __syncthreads();

    if (warp == 0) {
        float v = (lane < NUM_CLASSES) ? lg[lane] : -INFINITY;
        float m = v;
        #pragma unroll
        for (int off = 16; off; off >>= 1) m = fmaxf(m, __shfl_xor_sync(0xffffffffu, m, off));
        float e = (lane < NUM_CLASSES) ? expf(v - m) : 0.0f;
        float sum = e;
        #pragma unroll
        for (int off = 16; off; off >>= 1) sum += __shfl_xor_sync(0xffffffffu, sum, off);
        float prob = e / sum;
        float prob_next = __shfl_sync(0xffffffffu, prob, (lane + 1) & 31);

        if (lane < NUM_CLASSES-1) {
            int c = lane, cls = c + 1;
            const float* p = proposals + roi*4;
            float pw = p[2] - p[0], ph = p[3] - p[1];
            float px = p[0] + pw*0.5f, py = p[1] + ph*0.5f;
            float d0 = rg[cls*4+0], d1 = rg[cls*4+1], d2 = rg[cls*4+2], d3 = rg[cls*4+3];
            float cx = px + d0*pw;
            float cy = py + d1*ph;
            float w  = pw * expf(d2);
            float h  = ph * expf(d3);
            float Hc = (float)img_sizes[b*2 + 0];
            float Wd = (float)img_sizes[b*2 + 1];
            float bx1 = fminf(fmaxf(cx - w*0.5f, 0.0f), Wd);
            float by1 = fminf(fmaxf(cy - h*0.5f, 0.0f), Hc);
            float bx2 = fminf(fmaxf(cx + w*0.5f, 0.0f), Wd);
            float by2 = fminf(fmaxf(cy + h*0.5f, 0.0f), Hc);
            int g = b*NCAND + r*(NUM_CLASSES-1) + c;
            g_fb[g*4+0] = bx1; g_fb[g*4+1] = by1; g_fb[g*4+2] = bx2; g_fb[g*4+3] = by2;
            g_fs[g] = prob_next;
            g_valid[g] = (prob_next > SCORE_THRESH) ? 1 : 0;
            g_kept[g] = 0;
        }
    }
}

// ---------------- 6. per-class NMS ----------------
__global__ void k_nms() {
    int b = blockIdx.x / (NUM_CLASSES-1);
    int c = blockIdx.x % (NUM_CLASSES-1);
    int tid = threadIdx.x;

    __shared__ unsigned long long key[NPROP];
    __shared__ float bx1[NPROP], by1[NPROP], bx2[NPROP], by2[NPROP], ar[NPROP];
    __shared__ unsigned char keep[NPROP];

    int flat = tid*(NUM_CLASSES-1) + c;
    int g = b*NCAND + flat;
    float s = g_fs[g];
    bool v = g_valid[g] != 0;
    key[tid] = v ? ((((unsigned long long)flip_f32(s)) << 32) |
                   (unsigned long long)(0xFFFFFFFFu - (unsigned)flat)) : 0ull;

    for (int k = 2; k <= NPROP; k <<= 1) {
        for (int j = k >> 1; j > 0; j >>= 1) {
            __syncthreads();
            int ixj = tid ^ j;
            if (ixj > tid) {
                unsigned long long a = key[tid], bb_ = key[ixj];
                bool sw = ((tid & k) == 0) ? (a < bb_) : (a > bb_);
                if (sw) { key[tid] = bb_; key[ixj] = a; }
            }
        }
    }
    __syncthreads();

    unsigned long long kk = key[tid];
    bool vj = kk != 0ull;
    int sflat = -1;
    if (vj) {
        sflat = (int)(0xFFFFFFFFu - (unsigned)(kk & 0xFFFFFFFFu));
        const float* bp = g_fb + (b*NCAND + sflat)*4;
        bx1[tid] = bp[0]; by1[tid] = bp[1]; bx2[tid] = bp[2]; by2[tid] = bp[3];
        ar[tid] = (bp[2]-bp[0]) * (bp[3]-bp[1]);
    }
    keep[tid] = vj ? 1 : 0;
    int nv = __syncthreads_count(vj ? 1 : 0);

    for (int i = 0; i < nv; i++) {
        __syncthreads();
        if (!keep[i]) continue;
        if (tid > i && keep[tid]) {
            float xi1 = fmaxf(bx1[i], bx1[tid]);
            float yi1 = fmaxf(by1[i], by1[tid]);
            float xi2 = fminf(bx2[i], bx2[tid]);
            float yi2 = fminf(by2[i], by2[tid]);
            float inter = fmaxf(xi2 - xi1, 0.0f) * fmaxf(yi2 - yi1, 0.0f);
            float iou = inter / (ar[i] + ar[tid] - inter + 1e-9f);
            if (iou > NMS_THRESH) keep[tid] = 0;
        }
    }
    __syncthreads();
    if (vj && keep[tid]) g_kept[b*NCAND + sflat] = 1;
}

// ---------------- 7. final top-100 (compacted bitonic) ----------------
__global__ __launch_bounds__(1024)
void k_final(float* __restrict__ out) {
    int b = blockIdx.x;
    int tid = threadIdx.x;
    __shared__ unsigned long long key[4096];
    __shared__ int cnt;
    if (tid == 0) cnt = 0;
    __syncthreads();

    // compact kept candidates (order irrelevant; keys are unique and carry idx)
    for (int i = tid; i < NCAND; i += 1024) {
        if (g_kept[b*NCAND + i]) {
            int pos = atomicAdd(&cnt, 1);
            float s = g_fs[b*NCAND + i];
            key[pos] = (((unsigned long long)flip_f32(s)) << 32) |
                       (unsigned long long)(0xFFFFFFFFu - (unsigned)i);
        }
    }
    __syncthreads();
    int n = cnt;
    int P = 128;
    while (P < n) P <<= 1;          // next pow2 >= n (min 128 >= MAX_DET)
    for (int i = n + tid; i < P; i += 1024) key[i] = 0ull;
    __syncthreads();

    for (int k = 2; k <= P; k <<= 1) {
        for (int j = k >> 1; j > 0; j >>= 1) {
            for (int i = tid; i < P; i += 1024) {
                int ixj = i ^ j;
                if (ixj > i) {
                    unsigned long long a = key[i], bb_ = key[ixj];
                    bool sw = ((i & k) == 0) ? (a < bb_) : (a > bb_);
                    if (sw) { key[i] = bb_; key[ixj] = a; }
                }
            }
            __syncthreads();
        }
    }

    if (tid < MAX_DET) {
        unsigned long long k = (tid < n) ? key[tid] : 0ull;
        float b0=0,b1=0,b2=0,b3=0, sc=0, lb=0;
        if (k != 0ull) {
            int flat = (int)(0xFFFFFFFFu - (unsigned)(k & 0xFFFFFFFFu));
            const float* bp = g_fb + (b*NCAND + flat)*4;
            b0 = bp[0]; b1 = bp[1]; b2 = bp[2]; b3 = bp[3];
            sc = g_fs[b*NCAND + flat];
            lb = (float)(flat % (NUM_CLASSES-1) + 1);
        }
        out[b*MAX_DET*4 + tid*4 + 0] = b0;
        out[b*MAX_DET*4 + tid*4 + 1] = b1;
        out[b*MAX_DET*4 + tid*4 + 2] = b2;
        out[b*MAX_DET*4 + tid*4 + 3] = b3;
        out[BATCH*MAX_DET*4 + b*MAX_DET + tid] = sc;
        out[BATCH*MAX_DET*4 + BATCH*MAX_DET + b*MAX_DET + tid] = lb;
    }
}

// ---------------- launch ----------------
extern "C" void kernel_launch(void* const* d_in, const int* in_sizes, int n_in,
                              void* d_out, int out_size) {
    const float* features  = (const float*)d_in[0];
    const float* proposals = (const float*)d_in[1];
    const int*   img_sizes = (const int*)  d_in[2];
    const float* W1 = (const float*)d_in[3];
    const float* b1 = (const float*)d_in[4];
    const float* W2 = (const float*)d_in[5];
    const float* b2 = (const float*)d_in[6];
    const float* Wc = (const float*)d_in[7];
    const float* bc = (const float*)d_in[8];
    const float* Wb = (const float*)d_in[9];
    const float* bb = (const float*)d_in[10];
    float* out = (float*)d_out;

    float *pX, *pPart, *pH1, *pH2;
    cudaGetSymbolAddress((void**)&pX,    g_X);
    cudaGetSymbolAddress((void**)&pPart, g_part);
    cudaGetSymbolAddress((void**)&pH1,   g_H1);
    cudaGetSymbolAddress((void**)&pH2,   g_H2);

    cudaFuncSetAttribute(k_gemm_mma, cudaFuncAttributeMaxDynamicSharedMemorySize, SMEM_GEMM);

    k_transpose<<<dim3(32, 8, BATCH), dim3(32, 8)>>>(features);
    k_roialign<<<NROI, 256>>>(proposals);

    k_gemm_mma<<<dim3(2, 4, SPLITK), 256, SMEM_GEMM>>>(pX, W1, pPart, FEAT_DIM);
    k_reduce_bias_relu<<<(NROI*HID)/1024, 256>>>(pPart, b1, pH1);
    k_gemm_mma<<<dim3(2, 4, SPLITK), 256, SMEM_GEMM>>>(pH1, W2, pPart, HID);
    k_reduce_bias_relu<<<(NROI*HID)/1024, 256>>>(pPart, b2, pH2);

    k_head_post<<<NROI, 256>>>(Wc, bc, Wb, bb, proposals, img_sizes);
    k_nms<<<BATCH*(NUM_CLASSES-1), NPROP>>>();
    k_final<<<BATCH, 1024>>>(out);
}

// round 7
// speedup vs baseline: 1.6578x; 1.0290x over previous
#include <cuda_runtime.h>
#include <cstdint>
#include <math.h>

// ---------------- problem constants ----------------
#define BATCH 2
#define NPROP 128
#define NROI 256
#define IN_CH 256
#define FH 32
#define FW 32
#define ROI 7
#define FEAT_DIM 12544
#define HID 1024
#define NUM_CLASSES 21
#define NCAND 2560
#define MAX_DET 100
#define SPATIAL_SCALE (1.0f/32.0f)
#define SCORE_THRESH 0.05f
#define NMS_THRESH 0.5f
#define SPLITK 18

// ---------------- scratch ----------------
__device__ float g_featT[BATCH*FH*FW*IN_CH];
__device__ float g_X[NROI*FEAT_DIM];
__device__ float g_part[SPLITK*NROI*HID];
__device__ float g_H1[NROI*HID];
__device__ float g_H2[NROI*HID];
__device__ float g_fb[BATCH*NCAND*4];
__device__ float g_fs[BATCH*NCAND];
__device__ unsigned char g_valid[BATCH*NCAND];
__device__ unsigned char g_kept[BATCH*NCAND];

// ---------------- helpers ----------------
__device__ __forceinline__ uint32_t smem_u32(const void* p) {
    uint32_t a;
    asm("{ .reg .u64 t; cvta.to.shared.u64 t, %1; cvt.u32.u64 %0, t; }" : "=r"(a) : "l"(p));
    return a;
}
__device__ __forceinline__ unsigned int flip_f32(float f) {
    unsigned int u = __float_as_uint(f);
    return (u & 0x80000000u) ? ~u : (u | 0x80000000u);
}
__device__ __forceinline__ void splitf(float v, uint32_t& hi, uint32_t& lo) {
    uint32_t h = __float_as_uint(v) & 0xFFFFE000u;
    hi = h;
    lo = __float_as_uint(v - __uint_as_float(h));
}
__device__ __forceinline__ void mma8(float* d, const uint32_t* a, const uint32_t* b) {
    asm volatile(
        "mma.sync.aligned.m16n8k8.row.col.f32.tf32.tf32.f32 "
        "{%0,%1,%2,%3}, {%4,%5,%6,%7}, {%8,%9}, {%0,%1,%2,%3};"
        : "+f"(d[0]), "+f"(d[1]), "+f"(d[2]), "+f"(d[3])
        : "r"(a[0]), "r"(a[1]), "r"(a[2]), "r"(a[3]), "r"(b[0]), "r"(b[1]));
}
__device__ __forceinline__ void cp16(uint32_t sdst, const float* gsrc) {
    asm volatile("cp.async.cg.shared.global [%0], [%1], 16;" :: "r"(sdst), "l"(gsrc));
}

// ---------------- 1. feature transpose NCHW -> NHWC ----------------
__global__ void k_transpose(const float* __restrict__ f) {
    __shared__ float t[32][33];
    int b  = blockIdx.z;
    int c0 = blockIdx.y * 32;
    int w0 = blockIdx.x * 32;
    int tx = threadIdx.x, ty = threadIdx.y;
    #pragma unroll
    for (int i = ty; i < 32; i += 8)
        t[i][tx] = f[(b*IN_CH + c0 + i)*1024 + w0 + tx];
    __syncthreads();
    #pragma unroll
    for (int i = ty; i < 32; i += 8)
        g_featT[(b*1024 + w0 + i)*IN_CH + c0 + tx] = t[tx][i];
}

// ---------------- 2. RoIAlign (SMEM window + precomputed geometry) ----------------
#define WIN 8
#define NSAMP 196
__global__ __launch_bounds__(256)
void k_roialign(const float* __restrict__ proposals) {
    __shared__ float win[WIN*WIN*IN_CH];
    __shared__ float gw00[NSAMP], gw01[NSAMP], gw10[NSAMP], gw11[NSAMP];
    __shared__ int   gi00[NSAMP], gi01[NSAMP], gi10[NSAMP], gi11[NSAMP];

    int n = blockIdx.x;
    int b = n >> 7;
    int tid = threadIdx.x;

    const float* p = proposals + n*4;
    float x1 = p[0]*SPATIAL_SCALE, y1 = p[1]*SPATIAL_SCALE;
    float x2 = p[2]*SPATIAL_SCALE, y2 = p[3]*SPATIAL_SCALE;
    float rw = fmaxf(x2 - x1, 1.0f), rh = fmaxf(y2 - y1, 1.0f);
    float bw = rw / (float)ROI, bh = rh / (float)ROI;

    float ycmin = fminf(fmaxf(y1 + 0.25f*bh, 0.0f), (float)(FH-1));
    float xcmin = fminf(fmaxf(x1 + 0.25f*bw, 0.0f), (float)(FW-1));
    int y0w = (int)floorf(ycmin);
    int x0w = (int)floorf(xcmin);

    if (tid < NSAMP) {
        int bin = tid >> 2, s = tid & 3;
        int ph = bin / ROI, pw_ = bin - ph*ROI;
        int sy = s >> 1, sx = s & 1;
        float gy = (float)ph  + ((float)sy + 0.5f) * 0.5f;
        float gx = (float)pw_ + ((float)sx + 0.5f) * 0.5f;
        float yc = fminf(fmaxf(y1 + gy*bh, 0.0f), (float)(FH-1));
        float xc = fminf(fmaxf(x1 + gx*bw, 0.0f), (float)(FW-1));
        float y0f = floorf(yc), x0f = floorf(xc);
        int y0 = (int)y0f, x0 = (int)x0f;
        int y1i = min(y0 + 1, FH-1), x1i = min(x0 + 1, FW-1);
        float ly = yc - y0f, lx = xc - x0f;
        float hy = 1.0f - ly, hx = 1.0f - lx;
        int iy0 = y0 - y0w,  iy1 = y1i - y0w;
        int jx0 = x0 - x0w,  jx1 = x1i - x0w;
        gw00[tid] = hy*hx*0.25f; gw01[tid] = hy*lx*0.25f;
        gw10[tid] = ly*hx*0.25f; gw11[tid] = ly*lx*0.25f;
        gi00[tid] = (iy0*WIN + jx0)*IN_CH;
        gi01[tid] = (iy0*WIN + jx1)*IN_CH;
        gi10[tid] = (iy1*WIN + jx0)*IN_CH;
        gi11[tid] = (iy1*WIN + jx1)*IN_CH;
    }

    {
        int cell = tid >> 2, cq = tid & 3;
        int iy = cell >> 3, jx = cell & 7;
        int fy = min(y0w + iy, FH-1), fx = min(x0w + jx, FW-1);
        const float4* src = (const float4*)&g_featT[(((b*FH + fy)*FW) + fx)*IN_CH];
        float4* dst = (float4*)&win[cell*IN_CH];
        #pragma unroll
        for (int q = 0; q < 16; q++)
            dst[cq*16 + q] = src[cq*16 + q];
    }
    __syncthreads();

    int c = tid;
    float* outp = &g_X[(size_t)n*FEAT_DIM + c*(ROI*ROI)];
    #pragma unroll 7
    for (int bin = 0; bin < ROI*ROI; bin++) {
        float acc = 0.0f;
        #pragma unroll
        for (int s = 0; s < 4; s++) {
            int g = bin*4 + s;
            acc += gw00[g]*win[gi00[g] + c] + gw01[g]*win[gi01[g] + c]
                 + gw10[g]*win[gi10[g] + c] + gw11[g]*win[gi11[g] + c];
        }
        outp[bin] = acc;
    }
}

// ---------------- 3. tf32x3 mma.sync GEMM ----------------
// CTA tile 128x128, 8 warps (warp tile 32x64), 3-stage cp.async, 2 CTAs/SM.
#define ASTR 36
#define WSTR 36
#define A_FLOATS (128*ASTR)
#define W_FLOATS (128*WSTR)
#define STAGE_FLOATS (A_FLOATS + W_FLOATS)
#define SMEM_GEMM (3*STAGE_FLOATS*4)

__global__ __launch_bounds__(256, 2)
void k_gemm_mma(const float* __restrict__ A, const float* __restrict__ W,
                float* __restrict__ Cp, int K) {
    extern __shared__ float sm[];
    const uint32_t smb = smem_u32(sm);
    int tid = threadIdx.x;
    int wid = tid >> 5, lane = tid & 31;
    int wm = wid >> 1, wn = wid & 1;          // 4x2 warp grid, warp tile 32x64
    int m0 = blockIdx.x * 128;
    int n0 = blockIdx.y * 128;
    int z = blockIdx.z, Z = gridDim.z;
    int KT = K >> 5;
    int ntiles = (KT - z + Z - 1) / Z;

    float acc[2][8][4];
    #pragma unroll
    for (int i = 0; i < 2; i++)
        #pragma unroll
        for (int j = 0; j < 8; j++)
            #pragma unroll
            for (int q = 0; q < 4; q++) acc[i][j][q] = 0.0f;

    auto issue = [&](int ti) {
        int kt = z + ti * Z;
        uint32_t sa = smb + (uint32_t)((ti % 3) * STAGE_FLOATS) * 4u;
        uint32_t sw = sa + A_FLOATS * 4u;
        #pragma unroll
        for (int r = 0; r < 4; r++) {
            int t = tid + r*256;
            int row = t >> 3, q = t & 7;
            cp16(sa + (uint32_t)(row*ASTR + q*4)*4u,
                 &A[(size_t)(m0+row)*K + kt*32 + q*4]);
        }
        #pragma unroll
        for (int r = 0; r < 4; r++) {
            int t = tid + r*256;
            int row = t >> 3, q = t & 7;
            cp16(sw + (uint32_t)(row*WSTR + q*4)*4u,
                 &W[(size_t)(n0+row)*K + kt*32 + q*4]);
        }
        asm volatile("cp.async.commit_group;" ::: "memory");
    };

    issue(0);
    if (ntiles > 1) issue(1);

    for (int t = 0; t < ntiles; t++) {
        if (t + 1 < ntiles) asm volatile("cp.async.wait_group 1;" ::: "memory");
        else                asm volatile("cp.async.wait_group 0;" ::: "memory");
        __syncthreads();
        if (t + 2 < ntiles) issue(t + 2);

        const float* As = sm + (t % 3) * STAGE_FLOATS;
        const float* Ws = As + A_FLOATS;

        #pragma unroll
        for (int ks = 0; ks < 4; ks++) {
            int kc = ks*8 + (lane & 3);
            uint32_t aH[2][4], aL[2][4];
            #pragma unroll
            for (int mt = 0; mt < 2; mt++) {
                int r = wm*32 + mt*16 + (lane >> 2);
                splitf(As[r*ASTR + kc],         aH[mt][0], aL[mt][0]);
                splitf(As[(r+8)*ASTR + kc],     aH[mt][1], aL[mt][1]);
                splitf(As[r*ASTR + kc + 4],     aH[mt][2], aL[mt][2]);
                splitf(As[(r+8)*ASTR + kc + 4], aH[mt][3], aL[mt][3]);
            }
            #pragma unroll
            for (int half = 0; half < 2; half++) {
                uint32_t wH[4][2], wL[4][2];
                #pragma unroll
                for (int nt2 = 0; nt2 < 4; nt2++) {
                    int nr = wn*64 + (half*4 + nt2)*8 + (lane >> 2);
                    splitf(Ws[nr*WSTR + kc],     wH[nt2][0], wL[nt2][0]);
                    splitf(Ws[nr*WSTR + kc + 4], wH[nt2][1], wL[nt2][1]);
                }
                #pragma unroll
                for (int mt = 0; mt < 2; mt++)
                    #pragma unroll
                    for (int nt2 = 0; nt2 < 4; nt2++) {
                        float* d = acc[mt][half*4 + nt2];
                        mma8(d, aH[mt], wH[nt2]);
                        mma8(d, aL[mt], wH[nt2]);
                        mma8(d, aH[mt], wL[nt2]);
                    }
            }
        }
        __syncthreads();
    }

    float* C = Cp + (size_t)z * (NROI*HID);
    #pragma unroll
    for (int mt = 0; mt < 2; mt++) {
        int r = m0 + wm*32 + mt*16 + (lane >> 2);
        #pragma unroll
        for (int nt = 0; nt < 8; nt++) {
            int c = n0 + wn*64 + nt*8 + (lane & 3)*2;
            *(float2*)&C[(size_t)r*HID + c]     = make_float2(acc[mt][nt][0], acc[mt][nt][1]);
            *(float2*)&C[(size_t)(r+8)*HID + c] = make_float2(acc[mt][nt][2], acc[mt][nt][3]);
        }
    }
}

// ---------------- 4. split-K reduce + bias + relu ----------------
__global__ void k_reduce_bias_relu(const float* __restrict__ Cp,
                                   const float* __restrict__ bias,
                                   float* __restrict__ out) {
    int i = (blockIdx.x * blockDim.x + threadIdx.x) * 4;
    float4 s = make_float4(0.f, 0.f, 0.f, 0.f);
    #pragma unroll
    for (int k = 0; k < SPLITK; k++) {
        float4 v = *(const float4*)&Cp[(size_t)k*(NROI*HID) + i];
        s.x += v.x; s.y += v.y; s.z += v.z; s.w += v.w;
    }
    float4 bv = *(const float4*)&bias[i & (HID-1)];
    float4 o;
    o.x = fmaxf(s.x + bv.x, 0.f); o.y = fmaxf(s.y + bv.y, 0.f);
    o.z = fmaxf(s.z + bv.z, 0.f); o.w = fmaxf(s.w + bv.w, 0.f);
    *(float4*)&out[i] = o;
}

// ---------------- 5. fused heads + softmax + decode ----------------
__global__ __launch_bounds__(256)
void k_head_post(const float* __restrict__ Wc, const float* __restrict__ bc,
                 const float* __restrict__ Wb, const float* __restrict__ bb,
                 const float* __restrict__ proposals,
                 const int* __restrict__ img_sizes) {
    int roi = blockIdx.x;
    int b = roi >> 7, r = roi & 127;
    int tid = threadIdx.x;
    __shared__ float xs[HID];
    __shared__ float lg[NUM_CLASSES];
    __shared__ float rg[NUM_CLASSES*4];

    *(float4*)&xs[tid*4] = *(const float4*)&g_H2[(size_t)roi*HID + tid*4];
    __syncthreads();

    int warp = tid >> 5, lane = tid & 31;
    for (int o = warp; o < NUM_CLASSES*5; o += 8) {
        const float* Wrow; float bias;
        if (o < NUM_CLASSES) { Wrow = Wc + o*HID; bias = bc[o]; }
        else { Wrow = Wb + (o - NUM_CLASSES)*HID; bias = bb[o - NUM_CLASSES]; }
        float s = 0.0f;
        #pragma unroll
        for (int q = 0; q < 8; q++) {
            int k = (lane + q*32) * 4;
            float4 wv = *(const float4*)&Wrow[k];
            float4 xv = *(const float4*)&xs[k];
            s += wv.x*xv.x + wv.y*xv.y + wv.z*xv.z + wv.w*xv.w;
        }
        #pragma unroll
        for (int off = 16; off; off >>= 1) s += __shfl_down_sync(0xffffffffu, s, off);
        if (lane == 0) {
            s += bias;
            if (o < NUM_CLASSES) lg[o] = s;
            else rg[o - NUM_CLASSES] = s;
        }
    }
    __syncthreads();

    if (warp == 0) {
        float v = (lane < NUM_CLASSES) ? lg[lane] : -INFINITY;
        float m = v;
        #pragma unroll
        for (int off = 16; off; off >>= 1) m = fmaxf(m, __shfl_xor_sync(0xffffffffu, m, off));
        float e = (lane < NUM_CLASSES) ? expf(v - m) : 0.0f;
        float sum = e;
        #pragma unroll
        for (int off = 16; off; off >>= 1) sum += __shfl_xor_sync(0xffffffffu, sum, off);
        float prob = e / sum;
        float prob_next = __shfl_sync(0xffffffffu, prob, (lane + 1) & 31);

        if (lane < NUM_CLASSES-1) {
            int c = lane, cls = c + 1;
            const float* p = proposals + roi*4;
            float pw = p[2] - p[0], ph = p[3] - p[1];
            float px = p[0] + pw*0.5f, py = p[1] + ph*0.5f;
            float d0 = rg[cls*4+0], d1 = rg[cls*4+1], d2 = rg[cls*4+2], d3 = rg[cls*4+3];
            float cx = px + d0*pw;
            float cy = py + d1*ph;
            float w  = pw * expf(d2);
            float h  = ph * expf(d3);
            float Hc = (float)img_sizes[b*2 + 0];
            float Wd = (float)img_sizes[b*2 + 1];
            float bx1 = fminf(fmaxf(cx - w*0.5f, 0.0f), Wd);
            float by1 = fminf(fmaxf(cy - h*0.5f, 0.0f), Hc);
            float bx2 = fminf(fmaxf(cx + w*0.5f, 0.0f), Wd);
            float by2 = fminf(fmaxf(cy + h*0.5f, 0.0f), Hc);
            int g = b*NCAND + r*(NUM_CLASSES-1) + c;
            g_fb[g*4+0] = bx1; g_fb[g*4+1] = by1; g_fb[g*4+2] = bx2; g_fb[g*4+3] = by2;
            g_fs[g] = prob_next;
            g_valid[g] = (prob_next > SCORE_THRESH) ? 1 : 0;
            g_kept[g] = 0;
        }
    }
}

// ---------------- 6. per-class NMS ----------------
__global__ void k_nms() {
    int b = blockIdx.x / (NUM_CLASSES-1);
    int c = blockIdx.x % (NUM_CLASSES-1);
    int tid = threadIdx.x;

    __shared__ unsigned long long key[NPROP];
    __shared__ float bx1[NPROP], by1[NPROP], bx2[NPROP], by2[NPROP], ar[NPROP];
    __shared__ unsigned char keep[NPROP];

    int flat = tid*(NUM_CLASSES-1) + c;
    int g = b*NCAND + flat;
    float s = g_fs[g];
    bool v = g_valid[g] != 0;
    key[tid] = v ? ((((unsigned long long)flip_f32(s)) << 32) |
                   (unsigned long long)(0xFFFFFFFFu - (unsigned)flat)) : 0ull;

    for (int k = 2; k <= NPROP; k <<= 1) {
        for (int j = k >> 1; j > 0; j >>= 1) {
            __syncthreads();
            int ixj = tid ^ j;
            if (ixj > tid) {
                unsigned long long a = key[tid], bb_ = key[ixj];
                bool sw = ((tid & k) == 0) ? (a < bb_) : (a > bb_);
                if (sw) { key[tid] = bb_; key[ixj] = a; }
            }
        }
    }
    __syncthreads();

    unsigned long long kk = key[tid];
    bool vj = kk != 0ull;
    int sflat = -1;
    if (vj) {
        sflat = (int)(0xFFFFFFFFu - (unsigned)(kk & 0xFFFFFFFFu));
        const float* bp = g_fb + (b*NCAND + sflat)*4;
        bx1[tid] = bp[0]; by1[tid] = bp[1]; bx2[tid] = bp[2]; by2[tid] = bp[3];
        ar[tid] = (bp[2]-bp[0]) * (bp[3]-bp[1]);
    }
    keep[tid] = vj ? 1 : 0;
    int nv = __syncthreads_count(vj ? 1 : 0);

    for (int i = 0; i < nv; i++) {
        __syncthreads();
        if (!keep[i]) continue;
        if (tid > i && keep[tid]) {
            float xi1 = fmaxf(bx1[i], bx1[tid]);
            float yi1 = fmaxf(by1[i], by1[tid]);
            float xi2 = fminf(bx2[i], bx2[tid]);
            float yi2 = fminf(by2[i], by2[tid]);
            float inter = fmaxf(xi2 - xi1, 0.0f) * fmaxf(yi2 - yi1, 0.0f);
            float iou = inter / (ar[i] + ar[tid] - inter + 1e-9f);
            if (iou > NMS_THRESH) keep[tid] = 0;
        }
    }
    __syncthreads();
    if (vj && keep[tid]) g_kept[b*NCAND + sflat] = 1;
}

// ---------------- 7. final top-100 (compacted bitonic) ----------------
__global__ __launch_bounds__(1024)
void k_final(float* __restrict__ out) {
    int b = blockIdx.x;
    int tid = threadIdx.x;
    __shared__ unsigned long long key[4096];
    __shared__ int cnt;
    if (tid == 0) cnt = 0;
    __syncthreads();

    for (int i = tid; i < NCAND; i += 1024) {
        if (g_kept[b*NCAND + i]) {
            int pos = atomicAdd(&cnt, 1);
            float s = g_fs[b*NCAND + i];
            key[pos] = (((unsigned long long)flip_f32(s)) << 32) |
                       (unsigned long long)(0xFFFFFFFFu - (unsigned)i);
        }
    }
    __syncthreads();
    int n = cnt;
    int P = 128;
    while (P < n) P <<= 1;
    for (int i = n + tid; i < P; i += 1024) key[i] = 0ull;
    __syncthreads();

    for (int k = 2; k <= P; k <<= 1) {
        for (int j = k >> 1; j > 0; j >>= 1) {
            for (int i = tid; i < P; i += 1024) {
                int ixj = i ^ j;
                if (ixj > i) {
                    unsigned long long a = key[i], bb_ = key[ixj];
                    bool sw = ((i & k) == 0) ? (a < bb_) : (a > bb_);
                    if (sw) { key[i] = bb_; key[ixj] = a; }
                }
            }
            __syncthreads();
        }
    }

    if (tid < MAX_DET) {
        unsigned long long k = (tid < n) ? key[tid] : 0ull;
        float b0=0,b1=0,b2=0,b3=0, sc=0, lb=0;
        if (k != 0ull) {
            int flat = (int)(0xFFFFFFFFu - (unsigned)(k & 0xFFFFFFFFu));
            const float* bp = g_fb + (b*NCAND + flat)*4;
            b0 = bp[0]; b1 = bp[1]; b2 = bp[2]; b3 = bp[3];
            sc = g_fs[b*NCAND + flat];
            lb = (float)(flat % (NUM_CLASSES-1) + 1);
        }
        out[b*MAX_DET*4 + tid*4 + 0] = b0;
        out[b*MAX_DET*4 + tid*4 + 1] = b1;
        out[b*MAX_DET*4 + tid*4 + 2] = b2;
        out[b*MAX_DET*4 + tid*4 + 3] = b3;
        out[BATCH*MAX_DET*4 + b*MAX_DET + tid] = sc;
        out[BATCH*MAX_DET*4 + BATCH*MAX_DET + b*MAX_DET + tid] = lb;
    }
}

// ---------------- launch ----------------
extern "C" void kernel_launch(void* const* d_in, const int* in_sizes, int n_in,
                              void* d_out, int out_size) {
    const float* features  = (const float*)d_in[0];
    const float* proposals = (const float*)d_in[1];
    const int*   img_sizes = (const int*)  d_in[2];
    const float* W1 = (const float*)d_in[3];
    const float* b1 = (const float*)d_in[4];
    const float* W2 = (const float*)d_in[5];
    const float* b2 = (const float*)d_in[6];
    const float* Wc = (const float*)d_in[7];
    const float* bc = (const float*)d_in[8];
    const float* Wb = (const float*)d_in[9];
    const float* bb = (const float*)d_in[10];
    float* out = (float*)d_out;

    float *pX, *pPart, *pH1, *pH2;
    cudaGetSymbolAddress((void**)&pX,    g_X);
    cudaGetSymbolAddress((void**)&pPart, g_part);
    cudaGetSymbolAddress((void**)&pH1,   g_H1);
    cudaGetSymbolAddress((void**)&pH2,   g_H2);

    cudaFuncSetAttribute(k_gemm_mma, cudaFuncAttributeMaxDynamicSharedMemorySize, SMEM_GEMM);

    k_transpose<<<dim3(32, 8, BATCH), dim3(32, 8)>>>(features);
    k_roialign<<<NROI, 256>>>(proposals);

    // FC1: M=256 (2 tiles of 128), N=1024 (8 tiles of 128), splitK=18
    k_gemm_mma<<<dim3(2, 8, SPLITK), 256, SMEM_GEMM>>>(pX, W1, pPart, FEAT_DIM);
    k_reduce_bias_relu<<<(NROI*HID)/1024, 256>>>(pPart, b1, pH1);
    k_gemm_mma<<<dim3(2, 8, SPLITK), 256, SMEM_GEMM>>>(pH1, W2, pPart, HID);
    k_reduce_bias_relu<<<(NROI*HID)/1024, 256>>>(pPart, b2, pH2);

    k_head_post<<<NROI, 256>>>(Wc, bc, Wb, bb, proposals, img_sizes);
    k_nms<<<BATCH*(NUM_CLASSES-1), NPROP>>>();
    k_final<<<BATCH, 1024>>>(out);
}